// round 15
// baseline (speedup 1.0000x reference)
#include <cuda_runtime.h>
#include <cuda_bf16.h>
#include <math.h>
#include <stdint.h>

#define NN   20000
#define NE   320000
#define FIN  512
#define HID  256
#define LAT  128
#define H1   4
#define C1   64
#define NEG_SLOPE 0.2f
#define EPS_F 1e-16f

// ---------------- scratch ------------------------------------------------------
__device__ float g_xp1 [(size_t)NN * HID];
__device__ float g_hp23[(size_t)NN * 256];

__device__ __align__(16) __nv_bfloat16 g_xhi[(size_t)NN * FIN];
__device__ __align__(16) __nv_bfloat16 g_xlo[(size_t)NN * FIN];
__device__ __align__(16) __nv_bfloat16 g_hhi[(size_t)NN * HID];
__device__ __align__(16) __nv_bfloat16 g_hlo[(size_t)NN * HID];
__device__ __align__(16) __nv_bfloat16 g_bt1h[(size_t)HID * FIN];
__device__ __align__(16) __nv_bfloat16 g_bt1l[(size_t)HID * FIN];
__device__ __align__(16) __nv_bfloat16 g_bt23h[(size_t)256 * HID];
__device__ __align__(16) __nv_bfloat16 g_bt23l[(size_t)256 * HID];

__device__ float g_sd1[NN * H1], g_ss1[NN * H1];
__device__ float g_sd23[2 * NN];
__device__ float g_ss23[2 * NN];
__device__ float g_smax[8];

__device__ int  g_rowstart[NN + 1];
__device__ int  g_cursor[NN];
__device__ int2 g_epack[NE];

// ---------------- helpers ------------------------------------------------------
__device__ __forceinline__ void atomicMaxF(float* addr, float v) {
    if (v >= 0.0f) atomicMax((int*)addr, __float_as_int(v));
    else           atomicMin((unsigned int*)addr, __float_as_uint(v));
}
__device__ __forceinline__ float leaky(float a) { return a >= 0.f ? a : NEG_SLOPE * a; }

#define SWZ(off) ((off) ^ (((off) >> 3) & 0x70))

__device__ __forceinline__ void ldsm_x4(uint32_t& r0, uint32_t& r1, uint32_t& r2,
                                        uint32_t& r3, uint32_t a) {
    asm volatile("ldmatrix.sync.aligned.m8n8.x4.shared.b16 {%0,%1,%2,%3}, [%4];"
                 : "=r"(r0), "=r"(r1), "=r"(r2), "=r"(r3) : "r"(a));
}
__device__ __forceinline__ void ldsm_x2(uint32_t& r0, uint32_t& r1, uint32_t a) {
    asm volatile("ldmatrix.sync.aligned.m8n8.x2.shared.b16 {%0,%1}, [%2];"
                 : "=r"(r0), "=r"(r1) : "r"(a));
}
__device__ __forceinline__ void mma16816(float* c, const uint32_t* a, const uint32_t* b) {
    asm volatile("mma.sync.aligned.m16n8k16.row.col.f32.bf16.bf16.f32 "
                 "{%0,%1,%2,%3}, {%4,%5,%6,%7}, {%8,%9}, {%0,%1,%2,%3};"
                 : "+f"(c[0]), "+f"(c[1]), "+f"(c[2]), "+f"(c[3])
                 : "r"(a[0]), "r"(a[1]), "r"(a[2]), "r"(a[3]), "r"(b[0]), "r"(b[1]));
}
__device__ __forceinline__ void cp16(uint32_t saddr, const void* g) {
    asm volatile("cp.async.cg.shared.global [%0], [%1], 16;" :: "r"(saddr), "l"(g));
}
__device__ __forceinline__ void cp_commit() { asm volatile("cp.async.commit_group;"); }
template <int N> __device__ __forceinline__ void cp_wait() {
    asm volatile("cp.async.wait_group %0;" :: "n"(N));
}

// ---------------- x split (main stream) ------------------------------------------
__global__ void split4(const float4* __restrict__ in, __nv_bfloat162* __restrict__ hi,
                       __nv_bfloat162* __restrict__ lo, int n4) {
    int i = blockIdx.x * blockDim.x + threadIdx.x;
    if (i >= n4) return;
    float4 a = in[i];
    __nv_bfloat16 hx = __float2bfloat16(a.x), hy = __float2bfloat16(a.y);
    __nv_bfloat16 hz = __float2bfloat16(a.z), hw = __float2bfloat16(a.w);
    hi[i * 2 + 0] = __nv_bfloat162(hx, hy);
    hi[i * 2 + 1] = __nv_bfloat162(hz, hw);
    lo[i * 2 + 0] = __nv_bfloat162(__float2bfloat16(a.x - __bfloat162float(hx)),
                                   __float2bfloat16(a.y - __bfloat162float(hy)));
    lo[i * 2 + 1] = __nv_bfloat162(__float2bfloat16(a.z - __bfloat162float(hz)),
                                   __float2bfloat16(a.w - __bfloat162float(hw)));
}

// ---------------- weight prep (W splits + smax init + cursor zero), on s1 --------
__global__ void prepW(const float* __restrict__ W1,
                      __nv_bfloat16* __restrict__ bt1h, __nv_bfloat16* __restrict__ bt1l,
                      const float* __restrict__ Wmu, const float* __restrict__ Wlv,
                      __nv_bfloat16* __restrict__ bt23h, __nv_bfloat16* __restrict__ bt23l,
                      float* __restrict__ smax, int* __restrict__ cursor) {
    int i = blockIdx.x * blockDim.x + threadIdx.x;
    if (i < HID * FIN) {
        int n = i / FIN, k = i - n * FIN;
        float a = W1[(size_t)k * HID + n];
        __nv_bfloat16 h = __float2bfloat16(a);
        bt1h[i] = h;
        bt1l[i] = __float2bfloat16(a - __bfloat162float(h));
    }
    if (i < 256 * HID) {
        int n = i / HID, k = i - n * HID;
        float a = (n < LAT) ? Wmu[(size_t)k * LAT + n] : Wlv[(size_t)k * LAT + (n - LAT)];
        __nv_bfloat16 h = __float2bfloat16(a);
        bt23h[i] = h;
        bt23l[i] = __float2bfloat16(a - __bfloat162float(h));
    }
    if (i < NN) cursor[i] = 0;
    if (i < 8) smax[i] = -1e30f;
}

// ---------------- sort chain -----------------------------------------------------
__global__ void hist_kernel(const int* __restrict__ dst, int* __restrict__ cnt) {
    int e = blockIdx.x * blockDim.x + threadIdx.x;
    if (e < NE) atomicAdd(&cnt[dst[e]], 1);
}
// exclusive scan via warp shuffles; threads 0..999 own 20 elements each
__global__ void __launch_bounds__(1024) scan_kernel(int* __restrict__ cnt,
                                                    int* __restrict__ rowstart,
                                                    int* __restrict__ cursor) {
    __shared__ int wsum[32];
    const int t = threadIdx.x;
    const int lane = t & 31, warp = t >> 5;
    const int base = t * 20;
    int local[20];
    int s = 0;
    if (t < 1000) {
        const int4* p4 = (const int4*)(cnt + base);
        int4 v[5];
#pragma unroll
        for (int j = 0; j < 5; j++) v[j] = p4[j];
#pragma unroll
        for (int j = 0; j < 5; j++) {
            local[j * 4 + 0] = s; s += v[j].x;
            local[j * 4 + 1] = s; s += v[j].y;
            local[j * 4 + 2] = s; s += v[j].z;
            local[j * 4 + 3] = s; s += v[j].w;
        }
    }
    const int mysum = s;
    // warp inclusive scan
    int inc = s;
#pragma unroll
    for (int o = 1; o < 32; o <<= 1) {
        int n = __shfl_up_sync(0xffffffffu, inc, o);
        if (lane >= o) inc += n;
    }
    if (lane == 31) wsum[warp] = inc;
    __syncthreads();
    if (warp == 0) {
        int v = wsum[lane];
#pragma unroll
        for (int o = 1; o < 32; o <<= 1) {
            int n = __shfl_up_sync(0xffffffffu, v, o);
            if (lane >= o) v += n;
        }
        wsum[lane] = v;
    }
    __syncthreads();
    if (t < 1000) {
        int pre = (warp > 0 ? wsum[warp - 1] : 0) + (inc - mysum);
#pragma unroll
        for (int j = 0; j < 20; j++) {
            int v = pre + local[j];
            rowstart[base + j] = v;
            cursor[base + j] = v;
        }
    }
    if (t == 0) rowstart[NN] = NE;
}
__global__ void fillsort_kernel(const int* __restrict__ src, const int* __restrict__ dst,
                                const float* __restrict__ ew, int* __restrict__ cursor,
                                int2* __restrict__ epack) {
    int e = blockIdx.x * blockDim.x + threadIdx.x;
    if (e >= NE) return;
    int pos = atomicAdd(&cursor[dst[e]], 1);
    epack[pos] = make_int2(src[e], __float_as_int(ew[e]));
}

// ---------------- mma.sync GEMM, 144x256 tile (one-wave grid) -------------------
#define MT   144
#define PSA_H 0
#define PSA_L 18432
#define PSB_H 36864
#define PSB_L 69632
#define PBUF  102400

template<int SCOREMODE>
__global__ void __launch_bounds__(256)
gemm_mma(const __nv_bfloat16* __restrict__ Ahi, const __nv_bfloat16* __restrict__ Alo,
         const __nv_bfloat16* __restrict__ Bhi, const __nv_bfloat16* __restrict__ Blo,
         float* __restrict__ C, int M, int K,
         const float* __restrict__ attP, const float* __restrict__ attQ,
         float* __restrict__ sdo, float* __restrict__ sso,
         float* __restrict__ smax) {
    extern __shared__ char smem[];
    const uint32_t sb = (uint32_t)__cvta_generic_to_shared(smem);
    const int tid = threadIdx.x, wn = tid >> 5, lane = tid & 31;
    const int bm = blockIdx.y * MT;
    const int N = 256;

    float acc[9][4][4];
#pragma unroll
    for (int i = 0; i < 9; i++)
#pragma unroll
        for (int j = 0; j < 4; j++)
#pragma unroll
            for (int q = 0; q < 4; q++) acc[i][j][q] = 0.f;

    const int a_lrow = lane & 15;
    const int a_lbyte = ((lane >> 4) & 1) * 16;
    const int b_lrow = lane & 7;
    const int b_lbyte = ((lane >> 3) & 1) * 16;

    const int nchunks = K >> 6;

    auto stage = [&](int c, int buf) {
        const int k0 = c << 6;
        const uint32_t bufo = sb + buf * PBUF;
        for (int u = tid; u < MT * 8; u += 256) {
            int row = u >> 3, ch = u & 7;
            uint32_t soff = SWZ((uint32_t)(row * 128 + ch * 16));
            int arow = bm + row; if (arow >= M) arow = M - 1;
            size_t aidx = (size_t)arow * K + k0 + ch * 8;
            cp16(bufo + PSA_H + soff, Ahi + aidx);
            cp16(bufo + PSA_L + soff, Alo + aidx);
        }
        for (int u = tid; u < 256 * 8; u += 256) {
            int row = u >> 3, ch = u & 7;
            uint32_t soff = SWZ((uint32_t)(row * 128 + ch * 16));
            size_t bidx = (size_t)row * K + k0 + ch * 8;
            cp16(bufo + PSB_H + soff, Bhi + bidx);
            cp16(bufo + PSB_L + soff, Blo + bidx);
        }
        cp_commit();
    };

    stage(0, 0);
    for (int c = 0; c < nchunks; c++) {
        if (c + 1 < nchunks) { stage(c + 1, (c + 1) & 1); cp_wait<1>(); }
        else                 { cp_wait<0>(); }
        __syncthreads();
        const uint32_t bufo = sb + (c & 1) * PBUF;
#pragma unroll
        for (int ks = 0; ks < 4; ks++) {
            const int kb = ks * 32;
            uint32_t bh[4][2], bl[4][2];
#pragma unroll
            for (int nt = 0; nt < 4; nt++) {
                int row = wn * 32 + nt * 8 + b_lrow;
                uint32_t off = SWZ((uint32_t)(row * 128 + kb + b_lbyte));
                ldsm_x2(bh[nt][0], bh[nt][1], bufo + PSB_H + off);
                ldsm_x2(bl[nt][0], bl[nt][1], bufo + PSB_L + off);
            }
#pragma unroll
            for (int mt = 0; mt < 9; mt++) {
                uint32_t ah[4], al[4];
                int row = mt * 16 + a_lrow;
                uint32_t off = SWZ((uint32_t)(row * 128 + kb + a_lbyte));
                ldsm_x4(ah[0], ah[1], ah[2], ah[3], bufo + PSA_H + off);
                ldsm_x4(al[0], al[1], al[2], al[3], bufo + PSA_L + off);
#pragma unroll
                for (int nt = 0; nt < 4; nt++) {
                    mma16816(acc[mt][nt], ah, bh[nt]);
                    mma16816(acc[mt][nt], ah, bl[nt]);
                    mma16816(acc[mt][nt], al, bh[nt]);
                }
            }
        }
        __syncthreads();
    }

    // ---- store C ----
#pragma unroll
    for (int mt = 0; mt < 9; mt++) {
        int r0 = bm + mt * 16 + (lane >> 2);
#pragma unroll
        for (int nt = 0; nt < 4; nt++) {
            int col = wn * 32 + nt * 8 + (lane & 3) * 2;
            if (r0 < M)
                *(float2*)(C + (size_t)r0 * N + col) = make_float2(acc[mt][nt][0], acc[mt][nt][1]);
            if (r0 + 8 < M)
                *(float2*)(C + (size_t)(r0 + 8) * N + col) = make_float2(acc[mt][nt][2], acc[mt][nt][3]);
        }
    }

    // ---- in-CTA score finalization ----
    if constexpr (SCOREMODE != 0) {
        float* sbufD = (float*)smem;             // [8][MT]
        float* sbufS = sbufD + 8 * MT;           // [8][MT]
        const float* att;
        if constexpr (SCOREMODE == 1) att = attP + (wn >> 1) * (2 * C1);
        else                          att = (wn >> 2) ? attQ : attP;

#pragma unroll
        for (int mt = 0; mt < 9; mt++) {
            float pd0 = 0.f, ps0 = 0.f, pd8 = 0.f, ps8 = 0.f;
#pragma unroll
            for (int nt = 0; nt < 4; nt++) {
                int col = wn * 32 + nt * 8 + (lane & 3) * 2;
                float ad0, ad1, as0, as1;
                if constexpr (SCOREMODE == 1) {
                    int cidx = col & 63;
                    ad0 = __ldg(att + cidx);       ad1 = __ldg(att + cidx + 1);
                    as0 = __ldg(att + 64 + cidx);  as1 = __ldg(att + 64 + cidx + 1);
                } else {
                    int cidx = col & 127;
                    ad0 = __ldg(att + cidx);        ad1 = __ldg(att + cidx + 1);
                    as0 = __ldg(att + 128 + cidx);  as1 = __ldg(att + 128 + cidx + 1);
                }
                pd0 += acc[mt][nt][0] * ad0 + acc[mt][nt][1] * ad1;
                ps0 += acc[mt][nt][0] * as0 + acc[mt][nt][1] * as1;
                pd8 += acc[mt][nt][2] * ad0 + acc[mt][nt][3] * ad1;
                ps8 += acc[mt][nt][2] * as0 + acc[mt][nt][3] * as1;
            }
#pragma unroll
            for (int o = 1; o <= 2; o <<= 1) {
                pd0 += __shfl_xor_sync(0xffffffffu, pd0, o);
                ps0 += __shfl_xor_sync(0xffffffffu, ps0, o);
                pd8 += __shfl_xor_sync(0xffffffffu, pd8, o);
                ps8 += __shfl_xor_sync(0xffffffffu, ps8, o);
            }
            if ((lane & 3) == 0) {
                int rl = mt * 16 + (lane >> 2);
                sbufD[wn * MT + rl] = pd0;  sbufS[wn * MT + rl] = ps0;
                sbufD[wn * MT + rl + 8] = pd8;  sbufS[wn * MT + rl + 8] = ps8;
            }
        }
        __syncthreads();

        if constexpr (SCOREMODE == 1) {
            float mxd = -1e30f, mxs = -1e30f;
            for (int t = tid; t < MT * 4; t += 256) {
                int r = t >> 2, h = t & 3;
                int row = bm + r;
                if (row >= M) continue;
                float dsum = sbufD[(2 * h) * MT + r] + sbufD[(2 * h + 1) * MT + r];
                float ssum = sbufS[(2 * h) * MT + r] + sbufS[(2 * h + 1) * MT + r];
                sdo[row * 4 + h] = dsum;
                sso[row * 4 + h] = ssum;
                mxd = fmaxf(mxd, dsum);
                mxs = fmaxf(mxs, ssum);
            }
#pragma unroll
            for (int o = 16; o; o >>= 1) {
                mxd = fmaxf(mxd, __shfl_xor_sync(0xffffffffu, mxd, o));
                mxs = fmaxf(mxs, __shfl_xor_sync(0xffffffffu, mxs, o));
            }
            if (lane == 0) { atomicMaxF(&smax[0], mxd); atomicMaxF(&smax[1], mxs); }
        } else {
            float mxd = -1e30f, mxs = -1e30f;
            int mysel = tid & 1;
            for (int t = tid; t < MT * 2; t += 256) {
                int r = t >> 1, sel = t & 1;
                int row = bm + r;
                if (row >= M) continue;
                float dsum = 0.f, ssum = 0.f;
#pragma unroll
                for (int w = 0; w < 4; w++) {
                    dsum += sbufD[(sel * 4 + w) * MT + r];
                    ssum += sbufS[(sel * 4 + w) * MT + r];
                }
                sdo[row * 2 + sel] = dsum;
                sso[row * 2 + sel] = ssum;
                mxd = fmaxf(mxd, dsum);
                mxs = fmaxf(mxs, ssum);
            }
#pragma unroll
            for (int o = 2; o <= 16; o <<= 1) {
                mxd = fmaxf(mxd, __shfl_xor_sync(0xffffffffu, mxd, o));
                mxs = fmaxf(mxs, __shfl_xor_sync(0xffffffffu, mxs, o));
            }
            if (lane < 2) {
                atomicMaxF(&smax[2 + 2 * mysel], mxd);
                atomicMaxF(&smax[3 + 2 * mysel], mxs);
            }
        }
    }
}

// ---------------- layer-1 per-node aggregation ----------------------------------
__global__ void agg1(const int* __restrict__ rowstart, const int2* __restrict__ epack,
                     const float* __restrict__ sd, const float* __restrict__ ss,
                     const float* __restrict__ smax, const float* __restrict__ xp,
                     const float* __restrict__ bias,
                     __nv_bfloat162* __restrict__ hhi, __nv_bfloat162* __restrict__ hlo) {
    int d = (blockIdx.x * blockDim.x + threadIdx.x) >> 5;
    int lane = threadIdx.x & 31;
    if (d >= NN) return;
    const float M = leaky(__ldg(&smax[0]) + __ldg(&smax[1]));
    float4 sdv = *(const float4*)(sd + d * 4);
    const float sdA = (lane < 16) ? sdv.x : sdv.y;
    const float sdB = (lane < 16) ? sdv.z : sdv.w;

    float4 accA = make_float4(0.f, 0.f, 0.f, 0.f);
    float4 accB = make_float4(0.f, 0.f, 0.f, 0.f);
    float denA = 0.f, denB = 0.f;

    const int beg = rowstart[d], end = rowstart[d + 1];
    int i = beg;
    for (; i + 1 < end; i += 2) {
        int2 pa = epack[i], pb = epack[i + 1];
        int sa = pa.x, sbn = pb.x;
        float wa = __int_as_float(pa.y), wb = __int_as_float(pb.y);
        float4 ssa = *(const float4*)(ss + sa * 4);
        float4 ssb = *(const float4*)(ss + sbn * 4);
        const float4* xa = (const float4*)(xp + (size_t)sa * HID);
        const float4* xb = (const float4*)(xp + (size_t)sbn * HID);
        float4 va1 = xa[lane], va2 = xa[lane + 32];
        float4 vb1 = xb[lane], vb2 = xb[lane + 32];

        float ssaA = (lane < 16) ? ssa.x : ssa.y;
        float ssaB = (lane < 16) ? ssa.z : ssa.w;
        float exaA = expf(leaky(sdA + ssaA) - M);
        float exaB = expf(leaky(sdB + ssaB) - M);
        denA += exaA; denB += exaB;
        float caA = exaA * wa, caB = exaB * wa;
        accA.x = fmaf(caA, va1.x, accA.x); accA.y = fmaf(caA, va1.y, accA.y);
        accA.z = fmaf(caA, va1.z, accA.z); accA.w = fmaf(caA, va1.w, accA.w);
        accB.x = fmaf(caB, va2.x, accB.x); accB.y = fmaf(caB, va2.y, accB.y);
        accB.z = fmaf(caB, va2.z, accB.z); accB.w = fmaf(caB, va2.w, accB.w);

        float ssbA = (lane < 16) ? ssb.x : ssb.y;
        float ssbB = (lane < 16) ? ssb.z : ssb.w;
        float exbA = expf(leaky(sdA + ssbA) - M);
        float exbB = expf(leaky(sdB + ssbB) - M);
        denA += exbA; denB += exbB;
        float cbA = exbA * wb, cbB = exbB * wb;
        accA.x = fmaf(cbA, vb1.x, accA.x); accA.y = fmaf(cbA, vb1.y, accA.y);
        accA.z = fmaf(cbA, vb1.z, accA.z); accA.w = fmaf(cbA, vb1.w, accA.w);
        accB.x = fmaf(cbB, vb2.x, accB.x); accB.y = fmaf(cbB, vb2.y, accB.y);
        accB.z = fmaf(cbB, vb2.z, accB.z); accB.w = fmaf(cbB, vb2.w, accB.w);
    }
    if (i < end) {
        int2 p = epack[i];
        int s = p.x;
        float w = __int_as_float(p.y);
        float4 ssv = *(const float4*)(ss + s * 4);
        float ssA = (lane < 16) ? ssv.x : ssv.y;
        float ssB = (lane < 16) ? ssv.z : ssv.w;
        float exA = expf(leaky(sdA + ssA) - M);
        float exB = expf(leaky(sdB + ssB) - M);
        denA += exA; denB += exB;
        float cA = exA * w, cB = exB * w;
        const float4* xr = (const float4*)(xp + (size_t)s * HID);
        float4 v1 = xr[lane];
        float4 v2 = xr[lane + 32];
        accA.x = fmaf(cA, v1.x, accA.x); accA.y = fmaf(cA, v1.y, accA.y);
        accA.z = fmaf(cA, v1.z, accA.z); accA.w = fmaf(cA, v1.w, accA.w);
        accB.x = fmaf(cB, v2.x, accB.x); accB.y = fmaf(cB, v2.y, accB.y);
        accB.z = fmaf(cB, v2.z, accB.z); accB.w = fmaf(cB, v2.w, accB.w);
    }

    const float4 bA = *(const float4*)(bias + lane * 4);
    const float4 bB = *(const float4*)(bias + (lane + 32) * 4);
    float rA = 1.f / (denA + EPS_F), rB = 1.f / (denB + EPS_F);
    float4 oA, oB;
    float v;
    v = accA.x * rA + bA.x; oA.x = v > 0.f ? v : expm1f(v);
    v = accA.y * rA + bA.y; oA.y = v > 0.f ? v : expm1f(v);
    v = accA.z * rA + bA.z; oA.z = v > 0.f ? v : expm1f(v);
    v = accA.w * rA + bA.w; oA.w = v > 0.f ? v : expm1f(v);
    v = accB.x * rB + bB.x; oB.x = v > 0.f ? v : expm1f(v);
    v = accB.y * rB + bB.y; oB.y = v > 0.f ? v : expm1f(v);
    v = accB.z * rB + bB.z; oB.z = v > 0.f ? v : expm1f(v);
    v = accB.w * rB + bB.w; oB.w = v > 0.f ? v : expm1f(v);

    size_t base = (size_t)d * (HID / 2);
#pragma unroll
    for (int half = 0; half < 2; half++) {
        float4 o = half ? oB : oA;
        size_t idx = base + (half ? (lane + 32) : lane) * 2;
        __nv_bfloat16 hx = __float2bfloat16(o.x), hy = __float2bfloat16(o.y);
        __nv_bfloat16 hz = __float2bfloat16(o.z), hw = __float2bfloat16(o.w);
        hhi[idx + 0] = __nv_bfloat162(hx, hy);
        hhi[idx + 1] = __nv_bfloat162(hz, hw);
        hlo[idx + 0] = __nv_bfloat162(__float2bfloat16(o.x - __bfloat162float(hx)),
                                      __float2bfloat16(o.y - __bfloat162float(hy)));
        hlo[idx + 1] = __nv_bfloat162(__float2bfloat16(o.z - __bfloat162float(hz)),
                                      __float2bfloat16(o.w - __bfloat162float(hw)));
    }
}

// ---------------- mu/lv per-node aggregation ------------------------------------
__global__ void agg23(const int* __restrict__ rowstart, const int2* __restrict__ epack,
                      const float* __restrict__ sd23, const float* __restrict__ ss23,
                      const float* __restrict__ smax, const float* __restrict__ hp23,
                      const float* __restrict__ bmu, const float* __restrict__ blv,
                      float* __restrict__ omu, float* __restrict__ olv) {
    int d = (blockIdx.x * blockDim.x + threadIdx.x) >> 5;
    int lane = threadIdx.x & 31;
    if (d >= NN) return;
    const float M2 = leaky(__ldg(&smax[2]) + __ldg(&smax[3]));
    const float M3 = leaky(__ldg(&smax[4]) + __ldg(&smax[5]));
    float2 sdv = ((const float2*)sd23)[d];
    const float sdA = sdv.x, sdB = sdv.y;

    float4 accA = make_float4(0.f, 0.f, 0.f, 0.f);
    float4 accB = make_float4(0.f, 0.f, 0.f, 0.f);
    float denA = 0.f, denB = 0.f;

    const int beg = rowstart[d], end = rowstart[d + 1];
    int i = beg;
    for (; i + 1 < end; i += 2) {
        int2 pa = epack[i], pb = epack[i + 1];
        int sa = pa.x, sbn = pb.x;
        float wa = __int_as_float(pa.y), wb = __int_as_float(pb.y);
        float2 ssa = ((const float2*)ss23)[sa];
        float2 ssb = ((const float2*)ss23)[sbn];
        const float4* xa = (const float4*)(hp23 + (size_t)sa * 256);
        const float4* xb = (const float4*)(hp23 + (size_t)sbn * 256);
        float4 va1 = xa[lane], va2 = xa[lane + 32];
        float4 vb1 = xb[lane], vb2 = xb[lane + 32];

        float exaA = expf(leaky(sdA + ssa.x) - M2);
        float exaB = expf(leaky(sdB + ssa.y) - M3);
        denA += exaA; denB += exaB;
        float caA = exaA * wa, caB = exaB * wa;
        accA.x = fmaf(caA, va1.x, accA.x); accA.y = fmaf(caA, va1.y, accA.y);
        accA.z = fmaf(caA, va1.z, accA.z); accA.w = fmaf(caA, va1.w, accA.w);
        accB.x = fmaf(caB, va2.x, accB.x); accB.y = fmaf(caB, va2.y, accB.y);
        accB.z = fmaf(caB, va2.z, accB.z); accB.w = fmaf(caB, va2.w, accB.w);

        float exbA = expf(leaky(sdA + ssb.x) - M2);
        float exbB = expf(leaky(sdB + ssb.y) - M3);
        denA += exbA; denB += exbB;
        float cbA = exbA * wb, cbB = exbB * wb;
        accA.x = fmaf(cbA, vb1.x, accA.x); accA.y = fmaf(cbA, vb1.y, accA.y);
        accA.z = fmaf(cbA, vb1.z, accA.z); accA.w = fmaf(cbA, vb1.w, accA.w);
        accB.x = fmaf(cbB, vb2.x, accB.x); accB.y = fmaf(cbB, vb2.y, accB.y);
        accB.z = fmaf(cbB, vb2.z, accB.z); accB.w = fmaf(cbB, vb2.w, accB.w);
    }
    if (i < end) {
        int2 p = epack[i];
        int s = p.x;
        float w = __int_as_float(p.y);
        float2 ssv = ((const float2*)ss23)[s];
        float exA = expf(leaky(sdA + ssv.x) - M2);
        float exB = expf(leaky(sdB + ssv.y) - M3);
        denA += exA; denB += exB;
        float cA = exA * w, cB = exB * w;
        const float4* xr = (const float4*)(hp23 + (size_t)s * 256);
        float4 v1 = xr[lane];
        float4 v2 = xr[lane + 32];
        accA.x = fmaf(cA, v1.x, accA.x); accA.y = fmaf(cA, v1.y, accA.y);
        accA.z = fmaf(cA, v1.z, accA.z); accA.w = fmaf(cA, v1.w, accA.w);
        accB.x = fmaf(cB, v2.x, accB.x); accB.y = fmaf(cB, v2.y, accB.y);
        accB.z = fmaf(cB, v2.z, accB.z); accB.w = fmaf(cB, v2.w, accB.w);
    }
    float rA = 1.f / (denA + EPS_F), rB = 1.f / (denB + EPS_F);
    float4 bA = *(const float4*)(bmu + lane * 4);
    float4 bB = *(const float4*)(blv + lane * 4);
    *(float4*)(omu + (size_t)d * LAT + lane * 4) =
        make_float4(accA.x * rA + bA.x, accA.y * rA + bA.y,
                    accA.z * rA + bA.z, accA.w * rA + bA.w);
    *(float4*)(olv + (size_t)d * LAT + lane * 4) =
        make_float4(accB.x * rB + bB.x, accB.y * rB + bB.y,
                    accB.z * rB + bB.z, accB.w * rB + bB.w);
}

// ---------------- launch --------------------------------------------------------
static inline int cdiv(int a, int b) { return (a + b - 1) / b; }

struct PersistCtx {
    cudaStream_t s1;
    cudaEvent_t evRoot, evPrep, evSort;
    PersistCtx() {
        cudaStreamCreateWithFlags(&s1, cudaStreamNonBlocking);
        cudaEventCreateWithFlags(&evRoot, cudaEventDisableTiming);
        cudaEventCreateWithFlags(&evPrep, cudaEventDisableTiming);
        cudaEventCreateWithFlags(&evSort, cudaEventDisableTiming);
    }
};

extern "C" void kernel_launch(void* const* d_in, const int* in_sizes, int n_in,
                              void* d_out, int out_size) {
    static PersistCtx ctx;   // constructed on first call (correctness run) only

    const float* x     = (const float*)d_in[0];
    const int*   ei    = (const int*)  d_in[1];
    const float* ew    = (const float*)d_in[2];
    const float* W1    = (const float*)d_in[3];
    const float* att1  = (const float*)d_in[4];
    const float* b1    = (const float*)d_in[5];
    const float* Wmu   = (const float*)d_in[6];
    const float* attmu = (const float*)d_in[7];
    const float* bmu   = (const float*)d_in[8];
    const float* Wlv   = (const float*)d_in[9];
    const float* attlv = (const float*)d_in[10];
    const float* blv   = (const float*)d_in[11];

    const int* src = ei;
    const int* dst = ei + NE;
    float* out_mu = (float*)d_out;
    float* out_lv = out_mu + (size_t)NN * LAT;

    float *xp1, *hp23, *sd1, *ss1, *sd23, *ss23, *smax;
    __nv_bfloat16 *xhi, *xlo, *hhi, *hlo, *bt1h, *bt1l, *bt23h, *bt23l;
    int *rowstart, *cursor;
    int2 *epack;
    cudaGetSymbolAddress((void**)&xp1,   g_xp1);
    cudaGetSymbolAddress((void**)&hp23,  g_hp23);
    cudaGetSymbolAddress((void**)&xhi,   g_xhi);
    cudaGetSymbolAddress((void**)&xlo,   g_xlo);
    cudaGetSymbolAddress((void**)&hhi,   g_hhi);
    cudaGetSymbolAddress((void**)&hlo,   g_hlo);
    cudaGetSymbolAddress((void**)&bt1h,  g_bt1h);
    cudaGetSymbolAddress((void**)&bt1l,  g_bt1l);
    cudaGetSymbolAddress((void**)&bt23h, g_bt23h);
    cudaGetSymbolAddress((void**)&bt23l, g_bt23l);
    cudaGetSymbolAddress((void**)&sd1,   g_sd1);
    cudaGetSymbolAddress((void**)&ss1,   g_ss1);
    cudaGetSymbolAddress((void**)&sd23,  g_sd23);
    cudaGetSymbolAddress((void**)&ss23,  g_ss23);
    cudaGetSymbolAddress((void**)&smax,  g_smax);
    cudaGetSymbolAddress((void**)&rowstart, g_rowstart);
    cudaGetSymbolAddress((void**)&cursor,   g_cursor);
    cudaGetSymbolAddress((void**)&epack,    g_epack);

    cudaFuncSetAttribute(gemm_mma<1>, cudaFuncAttributeMaxDynamicSharedMemorySize, 2 * PBUF);
    cudaFuncSetAttribute(gemm_mma<2>, cudaFuncAttributeMaxDynamicSharedMemorySize, 2 * PBUF);

    const int TB = 256;
    const int MGRID = cdiv(NN, MT);   // 139 CTAs = one wave
    cudaStream_t s1 = ctx.s1;

    cudaEventRecord(ctx.evRoot, 0);
    cudaStreamWaitEvent(s1, ctx.evRoot, 0);

    // ----- s1: weight prep (+cursor zero), then edge sort chain -----
    prepW<<<cdiv(HID * FIN, TB), TB, 0, s1>>>(W1, bt1h, bt1l, Wmu, Wlv, bt23h, bt23l,
                                              smax, cursor);
    cudaEventRecord(ctx.evPrep, s1);
    hist_kernel<<<cdiv(NE, TB), TB, 0, s1>>>(dst, cursor);
    scan_kernel<<<1, 1024, 0, s1>>>(cursor, rowstart, cursor);
    fillsort_kernel<<<cdiv(NE, TB), TB, 0, s1>>>(src, dst, ew, cursor, epack);
    cudaEventRecord(ctx.evSort, s1);

    // ----- s0 (legacy): main chain -----
    split4<<<cdiv(NN * FIN / 4, TB), TB>>>((const float4*)x, (__nv_bfloat162*)xhi,
                                           (__nv_bfloat162*)xlo, NN * FIN / 4);
    cudaStreamWaitEvent(0, ctx.evPrep, 0);
    gemm_mma<1><<<dim3(1, MGRID), 256, 2 * PBUF>>>(
        xhi, xlo, bt1h, bt1l, xp1, NN, FIN, att1, nullptr, sd1, ss1, smax);
    cudaStreamWaitEvent(0, ctx.evSort, 0);
    agg1<<<cdiv(NN * 32, TB), TB>>>(rowstart, epack, sd1, ss1, smax, xp1, b1,
                                    (__nv_bfloat162*)hhi, (__nv_bfloat162*)hlo);
    gemm_mma<2><<<dim3(1, MGRID), 256, 2 * PBUF>>>(
        hhi, hlo, bt23h, bt23l, hp23, NN, HID, attmu, attlv, sd23, ss23, smax);
    agg23<<<cdiv(NN * 32, TB), TB>>>(rowstart, epack, sd23, ss23, smax,
                                     hp23, bmu, blv, out_mu, out_lv);
}

// round 16
// speedup vs baseline: 1.0734x; 1.0734x over previous
#include <cuda_runtime.h>
#include <cuda_bf16.h>
#include <math.h>
#include <stdint.h>

#define NN   20000
#define NE   320000
#define FIN  512
#define HID  256
#define LAT  128
#define H1   4
#define C1   64
#define NEG_SLOPE 0.2f
#define EPS_F 1e-16f

// ---------------- scratch ------------------------------------------------------
__device__ float g_xp1 [(size_t)NN * HID];
__device__ float g_hp23[(size_t)NN * 256];

__device__ __align__(16) __nv_bfloat16 g_hhi[(size_t)NN * HID];
__device__ __align__(16) __nv_bfloat16 g_hlo[(size_t)NN * HID];
__device__ __align__(16) __nv_bfloat16 g_bt1h[(size_t)HID * FIN];
__device__ __align__(16) __nv_bfloat16 g_bt1l[(size_t)HID * FIN];
__device__ __align__(16) __nv_bfloat16 g_bt23h[(size_t)256 * HID];
__device__ __align__(16) __nv_bfloat16 g_bt23l[(size_t)256 * HID];

__device__ float g_sd1[NN * H1], g_ss1[NN * H1];
__device__ float g_sd23[2 * NN];
__device__ float g_ss23[2 * NN];
__device__ float g_smax[8];

__device__ int  g_rowstart[NN + 1];
__device__ int  g_cursor[NN];
__device__ int2 g_epack[NE];

// ---------------- helpers ------------------------------------------------------
__device__ __forceinline__ void atomicMaxF(float* addr, float v) {
    if (v >= 0.0f) atomicMax((int*)addr, __float_as_int(v));
    else           atomicMin((unsigned int*)addr, __float_as_uint(v));
}
__device__ __forceinline__ float leaky(float a) { return a >= 0.f ? a : NEG_SLOPE * a; }

#define SWZ(off) ((off) ^ (((off) >> 3) & 0x70))

__device__ __forceinline__ void ldsm_x4(uint32_t& r0, uint32_t& r1, uint32_t& r2,
                                        uint32_t& r3, uint32_t a) {
    asm volatile("ldmatrix.sync.aligned.m8n8.x4.shared.b16 {%0,%1,%2,%3}, [%4];"
                 : "=r"(r0), "=r"(r1), "=r"(r2), "=r"(r3) : "r"(a));
}
__device__ __forceinline__ void ldsm_x2(uint32_t& r0, uint32_t& r1, uint32_t a) {
    asm volatile("ldmatrix.sync.aligned.m8n8.x2.shared.b16 {%0,%1}, [%2];"
                 : "=r"(r0), "=r"(r1) : "r"(a));
}
__device__ __forceinline__ void mma16816(float* c, const uint32_t* a, const uint32_t* b) {
    asm volatile("mma.sync.aligned.m16n8k16.row.col.f32.bf16.bf16.f32 "
                 "{%0,%1,%2,%3}, {%4,%5,%6,%7}, {%8,%9}, {%0,%1,%2,%3};"
                 : "+f"(c[0]), "+f"(c[1]), "+f"(c[2]), "+f"(c[3])
                 : "r"(a[0]), "r"(a[1]), "r"(a[2]), "r"(a[3]), "r"(b[0]), "r"(b[1]));
}
__device__ __forceinline__ void cp16(uint32_t saddr, const void* g) {
    asm volatile("cp.async.cg.shared.global [%0], [%1], 16;" :: "r"(saddr), "l"(g));
}
__device__ __forceinline__ void cp_commit() { asm volatile("cp.async.commit_group;"); }
template <int N> __device__ __forceinline__ void cp_wait() {
    asm volatile("cp.async.wait_group %0;" :: "n"(N));
}
__device__ __forceinline__ void split2(float x, float y, uint32_t& hi, uint32_t& lo) {
    __nv_bfloat16 hx = __float2bfloat16(x), hy = __float2bfloat16(y);
    __nv_bfloat162 h(hx, hy);
    __nv_bfloat162 l(__float2bfloat16(x - __bfloat162float(hx)),
                     __float2bfloat16(y - __bfloat162float(hy)));
    hi = *(uint32_t*)&h;
    lo = *(uint32_t*)&l;
}

// ---------------- weight prep (W splits + smax init + cursor zero), on s1 --------
__global__ void prepW(const float* __restrict__ W1,
                      __nv_bfloat16* __restrict__ bt1h, __nv_bfloat16* __restrict__ bt1l,
                      const float* __restrict__ Wmu, const float* __restrict__ Wlv,
                      __nv_bfloat16* __restrict__ bt23h, __nv_bfloat16* __restrict__ bt23l,
                      float* __restrict__ smax, int* __restrict__ cursor) {
    int i = blockIdx.x * blockDim.x + threadIdx.x;
    if (i < HID * FIN) {
        int n = i / FIN, k = i - n * FIN;
        float a = W1[(size_t)k * HID + n];
        __nv_bfloat16 h = __float2bfloat16(a);
        bt1h[i] = h;
        bt1l[i] = __float2bfloat16(a - __bfloat162float(h));
    }
    if (i < 256 * HID) {
        int n = i / HID, k = i - n * HID;
        float a = (n < LAT) ? Wmu[(size_t)k * LAT + n] : Wlv[(size_t)k * LAT + (n - LAT)];
        __nv_bfloat16 h = __float2bfloat16(a);
        bt23h[i] = h;
        bt23l[i] = __float2bfloat16(a - __bfloat162float(h));
    }
    if (i < NN) cursor[i] = 0;
    if (i < 8) smax[i] = -1e30f;
}

// ---------------- sort chain -----------------------------------------------------
__global__ void hist_kernel(const int* __restrict__ dst, int* __restrict__ cnt) {
    int e = blockIdx.x * blockDim.x + threadIdx.x;
    if (e < NE) atomicAdd(&cnt[dst[e]], 1);
}
__global__ void __launch_bounds__(1024) scan_kernel(int* __restrict__ cnt,
                                                    int* __restrict__ rowstart,
                                                    int* __restrict__ cursor) {
    __shared__ int wsum[32];
    const int t = threadIdx.x;
    const int lane = t & 31, warp = t >> 5;
    const int base = t * 20;
    int local[20];
    int s = 0;
    if (t < 1000) {
        const int4* p4 = (const int4*)(cnt + base);
        int4 v[5];
#pragma unroll
        for (int j = 0; j < 5; j++) v[j] = p4[j];
#pragma unroll
        for (int j = 0; j < 5; j++) {
            local[j * 4 + 0] = s; s += v[j].x;
            local[j * 4 + 1] = s; s += v[j].y;
            local[j * 4 + 2] = s; s += v[j].z;
            local[j * 4 + 3] = s; s += v[j].w;
        }
    }
    const int mysum = s;
    int inc = s;
#pragma unroll
    for (int o = 1; o < 32; o <<= 1) {
        int n = __shfl_up_sync(0xffffffffu, inc, o);
        if (lane >= o) inc += n;
    }
    if (lane == 31) wsum[warp] = inc;
    __syncthreads();
    if (warp == 0) {
        int v = wsum[lane];
#pragma unroll
        for (int o = 1; o < 32; o <<= 1) {
            int n = __shfl_up_sync(0xffffffffu, v, o);
            if (lane >= o) v += n;
        }
        wsum[lane] = v;
    }
    __syncthreads();
    if (t < 1000) {
        int pre = (warp > 0 ? wsum[warp - 1] : 0) + (inc - mysum);
#pragma unroll
        for (int j = 0; j < 20; j++) {
            int v = pre + local[j];
            rowstart[base + j] = v;
            cursor[base + j] = v;
        }
    }
    if (t == 0) rowstart[NN] = NE;
}
__global__ void fillsort_kernel(const int* __restrict__ src, const int* __restrict__ dst,
                                const float* __restrict__ ew, int* __restrict__ cursor,
                                int2* __restrict__ epack) {
    int e = blockIdx.x * blockDim.x + threadIdx.x;
    if (e >= NE) return;
    int pos = atomicAdd(&cursor[dst[e]], 1);
    epack[pos] = make_int2(src[e], __float_as_int(ew[e]));
}

// ================= gemm1 with fused fp32->bf16 A conversion =====================
// A staged as raw fp32 via cp.async (272B-padded rows); fragments built in regs.
// B double-buffered bf16 hi/lo as before. Score epilogue = SCOREMODE 1.
#define MT 144
#define CF_A0  0u
#define CF_A1  39168u        // 144*272
#define CF_BH0 78336u
#define CF_BL0 111104u
#define CF_BH1 143872u
#define CF_BL1 176640u
#define CF_TOTAL 209408

__global__ void __launch_bounds__(256)
gemm_conv(const float* __restrict__ Af,
          const __nv_bfloat16* __restrict__ Bhi, const __nv_bfloat16* __restrict__ Blo,
          float* __restrict__ C, int M, int K,
          const float* __restrict__ attP,
          float* __restrict__ sdo, float* __restrict__ sso,
          float* __restrict__ smax) {
    extern __shared__ char smem[];
    const uint32_t sb = (uint32_t)__cvta_generic_to_shared(smem);
    const int tid = threadIdx.x, wn = tid >> 5, lane = tid & 31;
    const int bm = blockIdx.y * MT;
    const int N = 256;

    float acc[9][4][4];
#pragma unroll
    for (int i = 0; i < 9; i++)
#pragma unroll
        for (int j = 0; j < 4; j++)
#pragma unroll
            for (int q = 0; q < 4; q++) acc[i][j][q] = 0.f;

    const int b_lrow = lane & 7;
    const int b_lbyte = ((lane >> 3) & 1) * 16;
    const int nchunks = K >> 6;

    auto stage = [&](int c, int buf) {
        const int k0 = c << 6;
        const uint32_t aof = buf ? CF_A1 : CF_A0;
        const uint32_t bhof = buf ? CF_BH1 : CF_BH0;
        const uint32_t blof = buf ? CF_BL1 : CF_BL0;
        // A: 144 rows x 64 fp32 (16 x 16B units per row)
        for (int u = tid; u < MT * 16; u += 256) {
            int row = u >> 4, unit = u & 15;
            int arow = bm + row; if (arow >= M) arow = M - 1;
            cp16(sb + aof + row * 272 + unit * 16,
                 Af + (size_t)arow * K + k0 + unit * 4);
        }
        // B: 256 rows x 64 bf16 (8 x 16B units per row), SWZ
        for (int u = tid; u < 256 * 8; u += 256) {
            int row = u >> 3, ch = u & 7;
            uint32_t soff = SWZ((uint32_t)(row * 128 + ch * 16));
            size_t bidx = (size_t)row * K + k0 + ch * 8;
            cp16(sb + bhof + soff, Bhi + bidx);
            cp16(sb + blof + soff, Blo + bidx);
        }
        cp_commit();
    };

    stage(0, 0);
    for (int c = 0; c < nchunks; c++) {
        if (c + 1 < nchunks) { stage(c + 1, (c + 1) & 1); cp_wait<1>(); }
        else                 { cp_wait<0>(); }
        __syncthreads();
        const int buf = c & 1;
        const char* abase = smem + (buf ? CF_A1 : CF_A0);
        const uint32_t bhof = sb + (buf ? CF_BH1 : CF_BH0);
        const uint32_t blof = sb + (buf ? CF_BL1 : CF_BL0);
#pragma unroll
        for (int ks = 0; ks < 4; ks++) {
            const int kb = ks * 32;
            uint32_t bh[4][2], bl[4][2];
#pragma unroll
            for (int nt = 0; nt < 4; nt++) {
                int row = wn * 32 + nt * 8 + b_lrow;
                uint32_t off = SWZ((uint32_t)(row * 128 + kb + b_lbyte));
                ldsm_x2(bh[nt][0], bh[nt][1], bhof + off);
                ldsm_x2(bl[nt][0], bl[nt][1], blof + off);
            }
            const int cc = ks * 16 + 2 * (lane & 3);
#pragma unroll
            for (int mt = 0; mt < 9; mt++) {
                const int r0 = mt * 16 + (lane >> 2);
                float2 f0 = *(const float2*)(abase + r0 * 272 + cc * 4);
                float2 f1 = *(const float2*)(abase + (r0 + 8) * 272 + cc * 4);
                float2 f2 = *(const float2*)(abase + r0 * 272 + (cc + 8) * 4);
                float2 f3 = *(const float2*)(abase + (r0 + 8) * 272 + (cc + 8) * 4);
                uint32_t ah[4], al[4];
                split2(f0.x, f0.y, ah[0], al[0]);
                split2(f1.x, f1.y, ah[1], al[1]);
                split2(f2.x, f2.y, ah[2], al[2]);
                split2(f3.x, f3.y, ah[3], al[3]);
#pragma unroll
                for (int nt = 0; nt < 4; nt++) {
                    mma16816(acc[mt][nt], ah, bh[nt]);
                    mma16816(acc[mt][nt], ah, bl[nt]);
                    mma16816(acc[mt][nt], al, bh[nt]);
                }
            }
        }
        __syncthreads();
    }

    // ---- store C ----
#pragma unroll
    for (int mt = 0; mt < 9; mt++) {
        int r0 = bm + mt * 16 + (lane >> 2);
#pragma unroll
        for (int nt = 0; nt < 4; nt++) {
            int col = wn * 32 + nt * 8 + (lane & 3) * 2;
            if (r0 < M)
                *(float2*)(C + (size_t)r0 * N + col) = make_float2(acc[mt][nt][0], acc[mt][nt][1]);
            if (r0 + 8 < M)
                *(float2*)(C + (size_t)(r0 + 8) * N + col) = make_float2(acc[mt][nt][2], acc[mt][nt][3]);
        }
    }

    // ---- in-CTA score finalization (SCOREMODE 1) ----
    {
        float* sbufD = (float*)smem;             // [8][MT]
        float* sbufS = sbufD + 8 * MT;
        const float* att = attP + (wn >> 1) * (2 * C1);
#pragma unroll
        for (int mt = 0; mt < 9; mt++) {
            float pd0 = 0.f, ps0 = 0.f, pd8 = 0.f, ps8 = 0.f;
#pragma unroll
            for (int nt = 0; nt < 4; nt++) {
                int col = wn * 32 + nt * 8 + (lane & 3) * 2;
                int cidx = col & 63;
                float ad0 = __ldg(att + cidx),      ad1 = __ldg(att + cidx + 1);
                float as0 = __ldg(att + 64 + cidx), as1 = __ldg(att + 64 + cidx + 1);
                pd0 += acc[mt][nt][0] * ad0 + acc[mt][nt][1] * ad1;
                ps0 += acc[mt][nt][0] * as0 + acc[mt][nt][1] * as1;
                pd8 += acc[mt][nt][2] * ad0 + acc[mt][nt][3] * ad1;
                ps8 += acc[mt][nt][2] * as0 + acc[mt][nt][3] * as1;
            }
#pragma unroll
            for (int o = 1; o <= 2; o <<= 1) {
                pd0 += __shfl_xor_sync(0xffffffffu, pd0, o);
                ps0 += __shfl_xor_sync(0xffffffffu, ps0, o);
                pd8 += __shfl_xor_sync(0xffffffffu, pd8, o);
                ps8 += __shfl_xor_sync(0xffffffffu, ps8, o);
            }
            if ((lane & 3) == 0) {
                int rl = mt * 16 + (lane >> 2);
                sbufD[wn * MT + rl] = pd0;  sbufS[wn * MT + rl] = ps0;
                sbufD[wn * MT + rl + 8] = pd8;  sbufS[wn * MT + rl + 8] = ps8;
            }
        }
        __syncthreads();

        float mxd = -1e30f, mxs = -1e30f;
        for (int t = tid; t < MT * 4; t += 256) {
            int r = t >> 2, h = t & 3;
            int row = bm + r;
            if (row >= M) continue;
            float dsum = sbufD[(2 * h) * MT + r] + sbufD[(2 * h + 1) * MT + r];
            float ssum = sbufS[(2 * h) * MT + r] + sbufS[(2 * h + 1) * MT + r];
            sdo[row * 4 + h] = dsum;
            sso[row * 4 + h] = ssum;
            mxd = fmaxf(mxd, dsum);
            mxs = fmaxf(mxs, ssum);
        }
#pragma unroll
        for (int o = 16; o; o >>= 1) {
            mxd = fmaxf(mxd, __shfl_xor_sync(0xffffffffu, mxd, o));
            mxs = fmaxf(mxs, __shfl_xor_sync(0xffffffffu, mxs, o));
        }
        if (lane == 0) { atomicMaxF(&smax[0], mxd); atomicMaxF(&smax[1], mxs); }
    }
}

// ---------------- gemm23 (bf16-staged, SCOREMODE 2) ------------------------------
#define PSA_H 0
#define PSA_L 18432
#define PSB_H 36864
#define PSB_L 69632
#define PBUF  102400

__global__ void __launch_bounds__(256)
gemm_mma2(const __nv_bfloat16* __restrict__ Ahi, const __nv_bfloat16* __restrict__ Alo,
          const __nv_bfloat16* __restrict__ Bhi, const __nv_bfloat16* __restrict__ Blo,
          float* __restrict__ C, int M, int K,
          const float* __restrict__ attP, const float* __restrict__ attQ,
          float* __restrict__ sdo, float* __restrict__ sso,
          float* __restrict__ smax) {
    extern __shared__ char smem[];
    const uint32_t sb = (uint32_t)__cvta_generic_to_shared(smem);
    const int tid = threadIdx.x, wn = tid >> 5, lane = tid & 31;
    const int bm = blockIdx.y * MT;
    const int N = 256;

    float acc[9][4][4];
#pragma unroll
    for (int i = 0; i < 9; i++)
#pragma unroll
        for (int j = 0; j < 4; j++)
#pragma unroll
            for (int q = 0; q < 4; q++) acc[i][j][q] = 0.f;

    const int a_lrow = lane & 15;
    const int a_lbyte = ((lane >> 4) & 1) * 16;
    const int b_lrow = lane & 7;
    const int b_lbyte = ((lane >> 3) & 1) * 16;
    const int nchunks = K >> 6;

    auto stage = [&](int c, int buf) {
        const int k0 = c << 6;
        const uint32_t bufo = sb + buf * PBUF;
        for (int u = tid; u < MT * 8; u += 256) {
            int row = u >> 3, ch = u & 7;
            uint32_t soff = SWZ((uint32_t)(row * 128 + ch * 16));
            int arow = bm + row; if (arow >= M) arow = M - 1;
            size_t aidx = (size_t)arow * K + k0 + ch * 8;
            cp16(bufo + PSA_H + soff, Ahi + aidx);
            cp16(bufo + PSA_L + soff, Alo + aidx);
        }
        for (int u = tid; u < 256 * 8; u += 256) {
            int row = u >> 3, ch = u & 7;
            uint32_t soff = SWZ((uint32_t)(row * 128 + ch * 16));
            size_t bidx = (size_t)row * K + k0 + ch * 8;
            cp16(bufo + PSB_H + soff, Bhi + bidx);
            cp16(bufo + PSB_L + soff, Blo + bidx);
        }
        cp_commit();
    };

    stage(0, 0);
    for (int c = 0; c < nchunks; c++) {
        if (c + 1 < nchunks) { stage(c + 1, (c + 1) & 1); cp_wait<1>(); }
        else                 { cp_wait<0>(); }
        __syncthreads();
        const uint32_t bufo = sb + (c & 1) * PBUF;
#pragma unroll
        for (int ks = 0; ks < 4; ks++) {
            const int kb = ks * 32;
            uint32_t bh[4][2], bl[4][2];
#pragma unroll
            for (int nt = 0; nt < 4; nt++) {
                int row = wn * 32 + nt * 8 + b_lrow;
                uint32_t off = SWZ((uint32_t)(row * 128 + kb + b_lbyte));
                ldsm_x2(bh[nt][0], bh[nt][1], bufo + PSB_H + off);
                ldsm_x2(bl[nt][0], bl[nt][1], bufo + PSB_L + off);
            }
#pragma unroll
            for (int mt = 0; mt < 9; mt++) {
                uint32_t ah[4], al[4];
                int row = mt * 16 + a_lrow;
                uint32_t off = SWZ((uint32_t)(row * 128 + kb + a_lbyte));
                ldsm_x4(ah[0], ah[1], ah[2], ah[3], bufo + PSA_H + off);
                ldsm_x4(al[0], al[1], al[2], al[3], bufo + PSA_L + off);
#pragma unroll
                for (int nt = 0; nt < 4; nt++) {
                    mma16816(acc[mt][nt], ah, bh[nt]);
                    mma16816(acc[mt][nt], ah, bl[nt]);
                    mma16816(acc[mt][nt], al, bh[nt]);
                }
            }
        }
        __syncthreads();
    }

#pragma unroll
    for (int mt = 0; mt < 9; mt++) {
        int r0 = bm + mt * 16 + (lane >> 2);
#pragma unroll
        for (int nt = 0; nt < 4; nt++) {
            int col = wn * 32 + nt * 8 + (lane & 3) * 2;
            if (r0 < M)
                *(float2*)(C + (size_t)r0 * N + col) = make_float2(acc[mt][nt][0], acc[mt][nt][1]);
            if (r0 + 8 < M)
                *(float2*)(C + (size_t)(r0 + 8) * N + col) = make_float2(acc[mt][nt][2], acc[mt][nt][3]);
        }
    }

    {
        float* sbufD = (float*)smem;
        float* sbufS = sbufD + 8 * MT;
        const float* att = (wn >> 2) ? attQ : attP;
#pragma unroll
        for (int mt = 0; mt < 9; mt++) {
            float pd0 = 0.f, ps0 = 0.f, pd8 = 0.f, ps8 = 0.f;
#pragma unroll
            for (int nt = 0; nt < 4; nt++) {
                int col = wn * 32 + nt * 8 + (lane & 3) * 2;
                int cidx = col & 127;
                float ad0 = __ldg(att + cidx),        ad1 = __ldg(att + cidx + 1);
                float as0 = __ldg(att + 128 + cidx),  as1 = __ldg(att + 128 + cidx + 1);
                pd0 += acc[mt][nt][0] * ad0 + acc[mt][nt][1] * ad1;
                ps0 += acc[mt][nt][0] * as0 + acc[mt][nt][1] * as1;
                pd8 += acc[mt][nt][2] * ad0 + acc[mt][nt][3] * ad1;
                ps8 += acc[mt][nt][2] * as0 + acc[mt][nt][3] * as1;
            }
#pragma unroll
            for (int o = 1; o <= 2; o <<= 1) {
                pd0 += __shfl_xor_sync(0xffffffffu, pd0, o);
                ps0 += __shfl_xor_sync(0xffffffffu, ps0, o);
                pd8 += __shfl_xor_sync(0xffffffffu, pd8, o);
                ps8 += __shfl_xor_sync(0xffffffffu, ps8, o);
            }
            if ((lane & 3) == 0) {
                int rl = mt * 16 + (lane >> 2);
                sbufD[wn * MT + rl] = pd0;  sbufS[wn * MT + rl] = ps0;
                sbufD[wn * MT + rl + 8] = pd8;  sbufS[wn * MT + rl + 8] = ps8;
            }
        }
        __syncthreads();

        float mxd = -1e30f, mxs = -1e30f;
        int mysel = tid & 1;
        for (int t = tid; t < MT * 2; t += 256) {
            int r = t >> 1, sel = t & 1;
            int row = bm + r;
            if (row >= M) continue;
            float dsum = 0.f, ssum = 0.f;
#pragma unroll
            for (int w = 0; w < 4; w++) {
                dsum += sbufD[(sel * 4 + w) * MT + r];
                ssum += sbufS[(sel * 4 + w) * MT + r];
            }
            sdo[row * 2 + sel] = dsum;
            sso[row * 2 + sel] = ssum;
            mxd = fmaxf(mxd, dsum);
            mxs = fmaxf(mxs, ssum);
        }
#pragma unroll
        for (int o = 2; o <= 16; o <<= 1) {
            mxd = fmaxf(mxd, __shfl_xor_sync(0xffffffffu, mxd, o));
            mxs = fmaxf(mxs, __shfl_xor_sync(0xffffffffu, mxs, o));
        }
        if (lane < 2) {
            atomicMaxF(&smax[2 + 2 * mysel], mxd);
            atomicMaxF(&smax[3 + 2 * mysel], mxs);
        }
    }
}

// ---------------- layer-1 per-node aggregation ----------------------------------
__global__ void agg1(const int* __restrict__ rowstart, const int2* __restrict__ epack,
                     const float* __restrict__ sd, const float* __restrict__ ss,
                     const float* __restrict__ smax, const float* __restrict__ xp,
                     const float* __restrict__ bias,
                     __nv_bfloat162* __restrict__ hhi, __nv_bfloat162* __restrict__ hlo) {
    int d = (blockIdx.x * blockDim.x + threadIdx.x) >> 5;
    int lane = threadIdx.x & 31;
    if (d >= NN) return;
    const float M = leaky(__ldg(&smax[0]) + __ldg(&smax[1]));
    float4 sdv = *(const float4*)(sd + d * 4);
    const float sdA = (lane < 16) ? sdv.x : sdv.y;
    const float sdB = (lane < 16) ? sdv.z : sdv.w;

    float4 accA = make_float4(0.f, 0.f, 0.f, 0.f);
    float4 accB = make_float4(0.f, 0.f, 0.f, 0.f);
    float denA = 0.f, denB = 0.f;

    const int beg = rowstart[d], end = rowstart[d + 1];
    int i = beg;
    for (; i + 1 < end; i += 2) {
        int2 pa = epack[i], pb = epack[i + 1];
        int sa = pa.x, sbn = pb.x;
        float wa = __int_as_float(pa.y), wb = __int_as_float(pb.y);
        float4 ssa = *(const float4*)(ss + sa * 4);
        float4 ssb = *(const float4*)(ss + sbn * 4);
        const float4* xa = (const float4*)(xp + (size_t)sa * HID);
        const float4* xb = (const float4*)(xp + (size_t)sbn * HID);
        float4 va1 = xa[lane], va2 = xa[lane + 32];
        float4 vb1 = xb[lane], vb2 = xb[lane + 32];

        float ssaA = (lane < 16) ? ssa.x : ssa.y;
        float ssaB = (lane < 16) ? ssa.z : ssa.w;
        float exaA = expf(leaky(sdA + ssaA) - M);
        float exaB = expf(leaky(sdB + ssaB) - M);
        denA += exaA; denB += exaB;
        float caA = exaA * wa, caB = exaB * wa;
        accA.x = fmaf(caA, va1.x, accA.x); accA.y = fmaf(caA, va1.y, accA.y);
        accA.z = fmaf(caA, va1.z, accA.z); accA.w = fmaf(caA, va1.w, accA.w);
        accB.x = fmaf(caB, va2.x, accB.x); accB.y = fmaf(caB, va2.y, accB.y);
        accB.z = fmaf(caB, va2.z, accB.z); accB.w = fmaf(caB, va2.w, accB.w);

        float ssbA = (lane < 16) ? ssb.x : ssb.y;
        float ssbB = (lane < 16) ? ssb.z : ssb.w;
        float exbA = expf(leaky(sdA + ssbA) - M);
        float exbB = expf(leaky(sdB + ssbB) - M);
        denA += exbA; denB += exbB;
        float cbA = exbA * wb, cbB = exbB * wb;
        accA.x = fmaf(cbA, vb1.x, accA.x); accA.y = fmaf(cbA, vb1.y, accA.y);
        accA.z = fmaf(cbA, vb1.z, accA.z); accA.w = fmaf(cbA, vb1.w, accA.w);
        accB.x = fmaf(cbB, vb2.x, accB.x); accB.y = fmaf(cbB, vb2.y, accB.y);
        accB.z = fmaf(cbB, vb2.z, accB.z); accB.w = fmaf(cbB, vb2.w, accB.w);
    }
    if (i < end) {
        int2 p = epack[i];
        int s = p.x;
        float w = __int_as_float(p.y);
        float4 ssv = *(const float4*)(ss + s * 4);
        float ssA = (lane < 16) ? ssv.x : ssv.y;
        float ssB = (lane < 16) ? ssv.z : ssv.w;
        float exA = expf(leaky(sdA + ssA) - M);
        float exB = expf(leaky(sdB + ssB) - M);
        denA += exA; denB += exB;
        float cA = exA * w, cB = exB * w;
        const float4* xr = (const float4*)(xp + (size_t)s * HID);
        float4 v1 = xr[lane];
        float4 v2 = xr[lane + 32];
        accA.x = fmaf(cA, v1.x, accA.x); accA.y = fmaf(cA, v1.y, accA.y);
        accA.z = fmaf(cA, v1.z, accA.z); accA.w = fmaf(cA, v1.w, accA.w);
        accB.x = fmaf(cB, v2.x, accB.x); accB.y = fmaf(cB, v2.y, accB.y);
        accB.z = fmaf(cB, v2.z, accB.z); accB.w = fmaf(cB, v2.w, accB.w);
    }

    const float4 bA = *(const float4*)(bias + lane * 4);
    const float4 bB = *(const float4*)(bias + (lane + 32) * 4);
    float rA = 1.f / (denA + EPS_F), rB = 1.f / (denB + EPS_F);
    float4 oA, oB;
    float v;
    v = accA.x * rA + bA.x; oA.x = v > 0.f ? v : expm1f(v);
    v = accA.y * rA + bA.y; oA.y = v > 0.f ? v : expm1f(v);
    v = accA.z * rA + bA.z; oA.z = v > 0.f ? v : expm1f(v);
    v = accA.w * rA + bA.w; oA.w = v > 0.f ? v : expm1f(v);
    v = accB.x * rB + bB.x; oB.x = v > 0.f ? v : expm1f(v);
    v = accB.y * rB + bB.y; oB.y = v > 0.f ? v : expm1f(v);
    v = accB.z * rB + bB.z; oB.z = v > 0.f ? v : expm1f(v);
    v = accB.w * rB + bB.w; oB.w = v > 0.f ? v : expm1f(v);

    size_t base = (size_t)d * (HID / 2);
#pragma unroll
    for (int half = 0; half < 2; half++) {
        float4 o = half ? oB : oA;
        size_t idx = base + (half ? (lane + 32) : lane) * 2;
        __nv_bfloat16 hx = __float2bfloat16(o.x), hy = __float2bfloat16(o.y);
        __nv_bfloat16 hz = __float2bfloat16(o.z), hw = __float2bfloat16(o.w);
        hhi[idx + 0] = __nv_bfloat162(hx, hy);
        hhi[idx + 1] = __nv_bfloat162(hz, hw);
        hlo[idx + 0] = __nv_bfloat162(__float2bfloat16(o.x - __bfloat162float(hx)),
                                      __float2bfloat16(o.y - __bfloat162float(hy)));
        hlo[idx + 1] = __nv_bfloat162(__float2bfloat16(o.z - __bfloat162float(hz)),
                                      __float2bfloat16(o.w - __bfloat162float(hw)));
    }
}

// ---------------- mu/lv per-node aggregation ------------------------------------
__global__ void agg23(const int* __restrict__ rowstart, const int2* __restrict__ epack,
                      const float* __restrict__ sd23, const float* __restrict__ ss23,
                      const float* __restrict__ smax, const float* __restrict__ hp23,
                      const float* __restrict__ bmu, const float* __restrict__ blv,
                      float* __restrict__ omu, float* __restrict__ olv) {
    int d = (blockIdx.x * blockDim.x + threadIdx.x) >> 5;
    int lane = threadIdx.x & 31;
    if (d >= NN) return;
    const float M2 = leaky(__ldg(&smax[2]) + __ldg(&smax[3]));
    const float M3 = leaky(__ldg(&smax[4]) + __ldg(&smax[5]));
    float2 sdv = ((const float2*)sd23)[d];
    const float sdA = sdv.x, sdB = sdv.y;

    float4 accA = make_float4(0.f, 0.f, 0.f, 0.f);
    float4 accB = make_float4(0.f, 0.f, 0.f, 0.f);
    float denA = 0.f, denB = 0.f;

    const int beg = rowstart[d], end = rowstart[d + 1];
    int i = beg;
    for (; i + 1 < end; i += 2) {
        int2 pa = epack[i], pb = epack[i + 1];
        int sa = pa.x, sbn = pb.x;
        float wa = __int_as_float(pa.y), wb = __int_as_float(pb.y);
        float2 ssa = ((const float2*)ss23)[sa];
        float2 ssb = ((const float2*)ss23)[sbn];
        const float4* xa = (const float4*)(hp23 + (size_t)sa * 256);
        const float4* xb = (const float4*)(hp23 + (size_t)sbn * 256);
        float4 va1 = xa[lane], va2 = xa[lane + 32];
        float4 vb1 = xb[lane], vb2 = xb[lane + 32];

        float exaA = expf(leaky(sdA + ssa.x) - M2);
        float exaB = expf(leaky(sdB + ssa.y) - M3);
        denA += exaA; denB += exaB;
        float caA = exaA * wa, caB = exaB * wa;
        accA.x = fmaf(caA, va1.x, accA.x); accA.y = fmaf(caA, va1.y, accA.y);
        accA.z = fmaf(caA, va1.z, accA.z); accA.w = fmaf(caA, va1.w, accA.w);
        accB.x = fmaf(caB, va2.x, accB.x); accB.y = fmaf(caB, va2.y, accB.y);
        accB.z = fmaf(caB, va2.z, accB.z); accB.w = fmaf(caB, va2.w, accB.w);

        float exbA = expf(leaky(sdA + ssb.x) - M2);
        float exbB = expf(leaky(sdB + ssb.y) - M3);
        denA += exbA; denB += exbB;
        float cbA = exbA * wb, cbB = exbB * wb;
        accA.x = fmaf(cbA, vb1.x, accA.x); accA.y = fmaf(cbA, vb1.y, accA.y);
        accA.z = fmaf(cbA, vb1.z, accA.z); accA.w = fmaf(cbA, vb1.w, accA.w);
        accB.x = fmaf(cbB, vb2.x, accB.x); accB.y = fmaf(cbB, vb2.y, accB.y);
        accB.z = fmaf(cbB, vb2.z, accB.z); accB.w = fmaf(cbB, vb2.w, accB.w);
    }
    if (i < end) {
        int2 p = epack[i];
        int s = p.x;
        float w = __int_as_float(p.y);
        float2 ssv = ((const float2*)ss23)[s];
        float exA = expf(leaky(sdA + ssv.x) - M2);
        float exB = expf(leaky(sdB + ssv.y) - M3);
        denA += exA; denB += exB;
        float cA = exA * w, cB = exB * w;
        const float4* xr = (const float4*)(hp23 + (size_t)s * 256);
        float4 v1 = xr[lane];
        float4 v2 = xr[lane + 32];
        accA.x = fmaf(cA, v1.x, accA.x); accA.y = fmaf(cA, v1.y, accA.y);
        accA.z = fmaf(cA, v1.z, accA.z); accA.w = fmaf(cA, v1.w, accA.w);
        accB.x = fmaf(cB, v2.x, accB.x); accB.y = fmaf(cB, v2.y, accB.y);
        accB.z = fmaf(cB, v2.z, accB.z); accB.w = fmaf(cB, v2.w, accB.w);
    }
    float rA = 1.f / (denA + EPS_F), rB = 1.f / (denB + EPS_F);
    float4 bA = *(const float4*)(bmu + lane * 4);
    float4 bB = *(const float4*)(blv + lane * 4);
    *(float4*)(omu + (size_t)d * LAT + lane * 4) =
        make_float4(accA.x * rA + bA.x, accA.y * rA + bA.y,
                    accA.z * rA + bA.z, accA.w * rA + bA.w);
    *(float4*)(olv + (size_t)d * LAT + lane * 4) =
        make_float4(accB.x * rB + bB.x, accB.y * rB + bB.y,
                    accB.z * rB + bB.z, accB.w * rB + bB.w);
}

// ---------------- launch --------------------------------------------------------
static inline int cdiv(int a, int b) { return (a + b - 1) / b; }

struct PersistCtx {
    cudaStream_t s1;
    cudaEvent_t evRoot, evPrep, evSort;
    PersistCtx() {
        cudaStreamCreateWithFlags(&s1, cudaStreamNonBlocking);
        cudaEventCreateWithFlags(&evRoot, cudaEventDisableTiming);
        cudaEventCreateWithFlags(&evPrep, cudaEventDisableTiming);
        cudaEventCreateWithFlags(&evSort, cudaEventDisableTiming);
    }
};

extern "C" void kernel_launch(void* const* d_in, const int* in_sizes, int n_in,
                              void* d_out, int out_size) {
    static PersistCtx ctx;

    const float* x     = (const float*)d_in[0];
    const int*   ei    = (const int*)  d_in[1];
    const float* ew    = (const float*)d_in[2];
    const float* W1    = (const float*)d_in[3];
    const float* att1  = (const float*)d_in[4];
    const float* b1    = (const float*)d_in[5];
    const float* Wmu   = (const float*)d_in[6];
    const float* attmu = (const float*)d_in[7];
    const float* bmu   = (const float*)d_in[8];
    const float* Wlv   = (const float*)d_in[9];
    const float* attlv = (const float*)d_in[10];
    const float* blv   = (const float*)d_in[11];

    const int* src = ei;
    const int* dst = ei + NE;
    float* out_mu = (float*)d_out;
    float* out_lv = out_mu + (size_t)NN * LAT;

    float *xp1, *hp23, *sd1, *ss1, *sd23, *ss23, *smax;
    __nv_bfloat16 *hhi, *hlo, *bt1h, *bt1l, *bt23h, *bt23l;
    int *rowstart, *cursor;
    int2 *epack;
    cudaGetSymbolAddress((void**)&xp1,   g_xp1);
    cudaGetSymbolAddress((void**)&hp23,  g_hp23);
    cudaGetSymbolAddress((void**)&hhi,   g_hhi);
    cudaGetSymbolAddress((void**)&hlo,   g_hlo);
    cudaGetSymbolAddress((void**)&bt1h,  g_bt1h);
    cudaGetSymbolAddress((void**)&bt1l,  g_bt1l);
    cudaGetSymbolAddress((void**)&bt23h, g_bt23h);
    cudaGetSymbolAddress((void**)&bt23l, g_bt23l);
    cudaGetSymbolAddress((void**)&sd1,   g_sd1);
    cudaGetSymbolAddress((void**)&ss1,   g_ss1);
    cudaGetSymbolAddress((void**)&sd23,  g_sd23);
    cudaGetSymbolAddress((void**)&ss23,  g_ss23);
    cudaGetSymbolAddress((void**)&smax,  g_smax);
    cudaGetSymbolAddress((void**)&rowstart, g_rowstart);
    cudaGetSymbolAddress((void**)&cursor,   g_cursor);
    cudaGetSymbolAddress((void**)&epack,    g_epack);

    cudaFuncSetAttribute(gemm_conv, cudaFuncAttributeMaxDynamicSharedMemorySize, CF_TOTAL);
    cudaFuncSetAttribute(gemm_mma2, cudaFuncAttributeMaxDynamicSharedMemorySize, 2 * PBUF);

    const int TB = 256;
    const int MGRID = cdiv(NN, MT);   // 139 CTAs = one wave
    cudaStream_t s1 = ctx.s1;

    cudaEventRecord(ctx.evRoot, 0);
    cudaStreamWaitEvent(s1, ctx.evRoot, 0);

    // ----- s1: weight prep (+cursor zero), then edge sort chain -----
    prepW<<<cdiv(HID * FIN, TB), TB, 0, s1>>>(W1, bt1h, bt1l, Wmu, Wlv, bt23h, bt23l,
                                              smax, cursor);
    cudaEventRecord(ctx.evPrep, s1);
    hist_kernel<<<cdiv(NE, TB), TB, 0, s1>>>(dst, cursor);
    scan_kernel<<<1, 1024, 0, s1>>>(cursor, rowstart, cursor);
    fillsort_kernel<<<cdiv(NE, TB), TB, 0, s1>>>(src, dst, ew, cursor, epack);
    cudaEventRecord(ctx.evSort, s1);

    // ----- s0 (legacy): main chain -----
    cudaStreamWaitEvent(0, ctx.evPrep, 0);
    gemm_conv<<<dim3(1, MGRID), 256, CF_TOTAL>>>(
        x, bt1h, bt1l, xp1, NN, FIN, att1, sd1, ss1, smax);
    cudaStreamWaitEvent(0, ctx.evSort, 0);
    agg1<<<cdiv(NN * 32, TB), TB>>>(rowstart, epack, sd1, ss1, smax, xp1, b1,
                                    (__nv_bfloat162*)hhi, (__nv_bfloat162*)hlo);
    gemm_mma2<<<dim3(1, MGRID), 256, 2 * PBUF>>>(
        hhi, hlo, bt23h, bt23l, hp23, NN, HID, attmu, attlv, sd23, ss23, smax);
    agg23<<<cdiv(NN * 32, TB), TB>>>(rowstart, epack, sd23, ss23, smax,
                                     hp23, bmu, blv, out_mu, out_lv);
}

// round 17
// speedup vs baseline: 1.1444x; 1.0662x over previous
#include <cuda_runtime.h>
#include <cuda_bf16.h>
#include <cuda_fp16.h>
#include <math.h>
#include <stdint.h>

#define NN   20000
#define NE   320000
#define FIN  512
#define HID  256
#define LAT  128
#define H1   4
#define C1   64
#define NEG_SLOPE 0.2f
#define EPS_F 1e-16f

// ---------------- scratch ------------------------------------------------------
__device__ __align__(16) __half g_xph [(size_t)NN * HID];    // layer-1 GEMM out (fp16)
__device__ __align__(16) __half g_hp23h[(size_t)NN * 256];   // mu|lv GEMM out (fp16)

__device__ __align__(16) __nv_bfloat16 g_hhi[(size_t)NN * HID];
__device__ __align__(16) __nv_bfloat16 g_hlo[(size_t)NN * HID];
__device__ __align__(16) __nv_bfloat16 g_bt1h[(size_t)HID * FIN];
__device__ __align__(16) __nv_bfloat16 g_bt1l[(size_t)HID * FIN];
__device__ __align__(16) __nv_bfloat16 g_bt23h[(size_t)256 * HID];
__device__ __align__(16) __nv_bfloat16 g_bt23l[(size_t)256 * HID];

__device__ float g_sd1[NN * H1], g_ss1[NN * H1];
__device__ float g_sd23[2 * NN];
__device__ float g_ss23[2 * NN];
__device__ float g_smax[8];

__device__ int  g_rowstart[NN + 1];
__device__ int  g_cursor[NN];
__device__ int2 g_epack[NE];

// ---------------- helpers ------------------------------------------------------
__device__ __forceinline__ void atomicMaxF(float* addr, float v) {
    if (v >= 0.0f) atomicMax((int*)addr, __float_as_int(v));
    else           atomicMin((unsigned int*)addr, __float_as_uint(v));
}
__device__ __forceinline__ float leaky(float a) { return a >= 0.f ? a : NEG_SLOPE * a; }

#define SWZ(off) ((off) ^ (((off) >> 3) & 0x70))

__device__ __forceinline__ void ldsm_x4(uint32_t& r0, uint32_t& r1, uint32_t& r2,
                                        uint32_t& r3, uint32_t a) {
    asm volatile("ldmatrix.sync.aligned.m8n8.x4.shared.b16 {%0,%1,%2,%3}, [%4];"
                 : "=r"(r0), "=r"(r1), "=r"(r2), "=r"(r3) : "r"(a));
}
__device__ __forceinline__ void ldsm_x2(uint32_t& r0, uint32_t& r1, uint32_t a) {
    asm volatile("ldmatrix.sync.aligned.m8n8.x2.shared.b16 {%0,%1}, [%2];"
                 : "=r"(r0), "=r"(r1) : "r"(a));
}
__device__ __forceinline__ void mma16816(float* c, const uint32_t* a, const uint32_t* b) {
    asm volatile("mma.sync.aligned.m16n8k16.row.col.f32.bf16.bf16.f32 "
                 "{%0,%1,%2,%3}, {%4,%5,%6,%7}, {%8,%9}, {%0,%1,%2,%3};"
                 : "+f"(c[0]), "+f"(c[1]), "+f"(c[2]), "+f"(c[3])
                 : "r"(a[0]), "r"(a[1]), "r"(a[2]), "r"(a[3]), "r"(b[0]), "r"(b[1]));
}
__device__ __forceinline__ void cp16(uint32_t saddr, const void* g) {
    asm volatile("cp.async.cg.shared.global [%0], [%1], 16;" :: "r"(saddr), "l"(g));
}
__device__ __forceinline__ void cp_commit() { asm volatile("cp.async.commit_group;"); }
template <int N> __device__ __forceinline__ void cp_wait() {
    asm volatile("cp.async.wait_group %0;" :: "n"(N));
}
__device__ __forceinline__ void split2(float x, float y, uint32_t& hi, uint32_t& lo) {
    __nv_bfloat16 hx = __float2bfloat16(x), hy = __float2bfloat16(y);
    __nv_bfloat162 h(hx, hy);
    __nv_bfloat162 l(__float2bfloat16(x - __bfloat162float(hx)),
                     __float2bfloat16(y - __bfloat162float(hy)));
    hi = *(uint32_t*)&h;
    lo = *(uint32_t*)&l;
}

// ---------------- weight prep (W splits + smax init + cursor zero), on s1 --------
__global__ void prepW(const float* __restrict__ W1,
                      __nv_bfloat16* __restrict__ bt1h, __nv_bfloat16* __restrict__ bt1l,
                      const float* __restrict__ Wmu, const float* __restrict__ Wlv,
                      __nv_bfloat16* __restrict__ bt23h, __nv_bfloat16* __restrict__ bt23l,
                      float* __restrict__ smax, int* __restrict__ cursor) {
    int i = blockIdx.x * blockDim.x + threadIdx.x;
    if (i < HID * FIN) {
        int n = i / FIN, k = i - n * FIN;
        float a = W1[(size_t)k * HID + n];
        __nv_bfloat16 h = __float2bfloat16(a);
        bt1h[i] = h;
        bt1l[i] = __float2bfloat16(a - __bfloat162float(h));
    }
    if (i < 256 * HID) {
        int n = i / HID, k = i - n * HID;
        float a = (n < LAT) ? Wmu[(size_t)k * LAT + n] : Wlv[(size_t)k * LAT + (n - LAT)];
        __nv_bfloat16 h = __float2bfloat16(a);
        bt23h[i] = h;
        bt23l[i] = __float2bfloat16(a - __bfloat162float(h));
    }
    if (i < NN) cursor[i] = 0;
    if (i < 8) smax[i] = -1e30f;
}

// ---------------- sort chain -----------------------------------------------------
__global__ void hist_kernel(const int* __restrict__ dst, int* __restrict__ cnt) {
    int e = blockIdx.x * blockDim.x + threadIdx.x;
    if (e < NE) atomicAdd(&cnt[dst[e]], 1);
}
__global__ void __launch_bounds__(1024) scan_kernel(int* __restrict__ cnt,
                                                    int* __restrict__ rowstart,
                                                    int* __restrict__ cursor) {
    __shared__ int wsum[32];
    const int t = threadIdx.x;
    const int lane = t & 31, warp = t >> 5;
    const int base = t * 20;
    int local[20];
    int s = 0;
    if (t < 1000) {
        const int4* p4 = (const int4*)(cnt + base);
        int4 v[5];
#pragma unroll
        for (int j = 0; j < 5; j++) v[j] = p4[j];
#pragma unroll
        for (int j = 0; j < 5; j++) {
            local[j * 4 + 0] = s; s += v[j].x;
            local[j * 4 + 1] = s; s += v[j].y;
            local[j * 4 + 2] = s; s += v[j].z;
            local[j * 4 + 3] = s; s += v[j].w;
        }
    }
    const int mysum = s;
    int inc = s;
#pragma unroll
    for (int o = 1; o < 32; o <<= 1) {
        int n = __shfl_up_sync(0xffffffffu, inc, o);
        if (lane >= o) inc += n;
    }
    if (lane == 31) wsum[warp] = inc;
    __syncthreads();
    if (warp == 0) {
        int v = wsum[lane];
#pragma unroll
        for (int o = 1; o < 32; o <<= 1) {
            int n = __shfl_up_sync(0xffffffffu, v, o);
            if (lane >= o) v += n;
        }
        wsum[lane] = v;
    }
    __syncthreads();
    if (t < 1000) {
        int pre = (warp > 0 ? wsum[warp - 1] : 0) + (inc - mysum);
#pragma unroll
        for (int j = 0; j < 20; j++) {
            int v = pre + local[j];
            rowstart[base + j] = v;
            cursor[base + j] = v;
        }
    }
    if (t == 0) rowstart[NN] = NE;
}
__global__ void fillsort_kernel(const int* __restrict__ src, const int* __restrict__ dst,
                                const float* __restrict__ ew, int* __restrict__ cursor,
                                int2* __restrict__ epack) {
    int e = blockIdx.x * blockDim.x + threadIdx.x;
    if (e >= NE) return;
    int pos = atomicAdd(&cursor[dst[e]], 1);
    epack[pos] = make_int2(src[e], __float_as_int(ew[e]));
}

// ================= gemm1 with fused fp32->bf16 A conversion, fp16 C =============
#define MT 144
#define CF_A0  0u
#define CF_A1  39168u
#define CF_BH0 78336u
#define CF_BL0 111104u
#define CF_BH1 143872u
#define CF_BL1 176640u
#define CF_TOTAL 209408

__global__ void __launch_bounds__(256)
gemm_conv(const float* __restrict__ Af,
          const __nv_bfloat16* __restrict__ Bhi, const __nv_bfloat16* __restrict__ Blo,
          __half* __restrict__ C, int M, int K,
          const float* __restrict__ attP,
          float* __restrict__ sdo, float* __restrict__ sso,
          float* __restrict__ smax) {
    extern __shared__ char smem[];
    const uint32_t sb = (uint32_t)__cvta_generic_to_shared(smem);
    const int tid = threadIdx.x, wn = tid >> 5, lane = tid & 31;
    const int bm = blockIdx.y * MT;
    const int N = 256;

    float acc[9][4][4];
#pragma unroll
    for (int i = 0; i < 9; i++)
#pragma unroll
        for (int j = 0; j < 4; j++)
#pragma unroll
            for (int q = 0; q < 4; q++) acc[i][j][q] = 0.f;

    const int b_lrow = lane & 7;
    const int b_lbyte = ((lane >> 3) & 1) * 16;
    const int nchunks = K >> 6;

    auto stage = [&](int c, int buf) {
        const int k0 = c << 6;
        const uint32_t aof = buf ? CF_A1 : CF_A0;
        const uint32_t bhof = buf ? CF_BH1 : CF_BH0;
        const uint32_t blof = buf ? CF_BL1 : CF_BL0;
        for (int u = tid; u < MT * 16; u += 256) {
            int row = u >> 4, unit = u & 15;
            int arow = bm + row; if (arow >= M) arow = M - 1;
            cp16(sb + aof + row * 272 + unit * 16,
                 Af + (size_t)arow * K + k0 + unit * 4);
        }
        for (int u = tid; u < 256 * 8; u += 256) {
            int row = u >> 3, ch = u & 7;
            uint32_t soff = SWZ((uint32_t)(row * 128 + ch * 16));
            size_t bidx = (size_t)row * K + k0 + ch * 8;
            cp16(sb + bhof + soff, Bhi + bidx);
            cp16(sb + blof + soff, Blo + bidx);
        }
        cp_commit();
    };

    stage(0, 0);
    for (int c = 0; c < nchunks; c++) {
        if (c + 1 < nchunks) { stage(c + 1, (c + 1) & 1); cp_wait<1>(); }
        else                 { cp_wait<0>(); }
        __syncthreads();
        const int buf = c & 1;
        const char* abase = smem + (buf ? CF_A1 : CF_A0);
        const uint32_t bhof = sb + (buf ? CF_BH1 : CF_BH0);
        const uint32_t blof = sb + (buf ? CF_BL1 : CF_BL0);
#pragma unroll
        for (int ks = 0; ks < 4; ks++) {
            const int kb = ks * 32;
            uint32_t bh[4][2], bl[4][2];
#pragma unroll
            for (int nt = 0; nt < 4; nt++) {
                int row = wn * 32 + nt * 8 + b_lrow;
                uint32_t off = SWZ((uint32_t)(row * 128 + kb + b_lbyte));
                ldsm_x2(bh[nt][0], bh[nt][1], bhof + off);
                ldsm_x2(bl[nt][0], bl[nt][1], blof + off);
            }
            const int cc = ks * 16 + 2 * (lane & 3);
#pragma unroll
            for (int mt = 0; mt < 9; mt++) {
                const int r0 = mt * 16 + (lane >> 2);
                float2 f0 = *(const float2*)(abase + r0 * 272 + cc * 4);
                float2 f1 = *(const float2*)(abase + (r0 + 8) * 272 + cc * 4);
                float2 f2 = *(const float2*)(abase + r0 * 272 + (cc + 8) * 4);
                float2 f3 = *(const float2*)(abase + (r0 + 8) * 272 + (cc + 8) * 4);
                uint32_t ah[4], al[4];
                split2(f0.x, f0.y, ah[0], al[0]);
                split2(f1.x, f1.y, ah[1], al[1]);
                split2(f2.x, f2.y, ah[2], al[2]);
                split2(f3.x, f3.y, ah[3], al[3]);
#pragma unroll
                for (int nt = 0; nt < 4; nt++) {
                    mma16816(acc[mt][nt], ah, bh[nt]);
                    mma16816(acc[mt][nt], ah, bl[nt]);
                    mma16816(acc[mt][nt], al, bh[nt]);
                }
            }
        }
        __syncthreads();
    }

    // ---- store C (fp16) ----
#pragma unroll
    for (int mt = 0; mt < 9; mt++) {
        int r0 = bm + mt * 16 + (lane >> 2);
#pragma unroll
        for (int nt = 0; nt < 4; nt++) {
            int col = wn * 32 + nt * 8 + (lane & 3) * 2;
            if (r0 < M)
                *(__half2*)(C + (size_t)r0 * N + col) =
                    __floats2half2_rn(acc[mt][nt][0], acc[mt][nt][1]);
            if (r0 + 8 < M)
                *(__half2*)(C + (size_t)(r0 + 8) * N + col) =
                    __floats2half2_rn(acc[mt][nt][2], acc[mt][nt][3]);
        }
    }

    // ---- in-CTA score finalization (layer 1) ----
    {
        float* sbufD = (float*)smem;
        float* sbufS = sbufD + 8 * MT;
        const float* att = attP + (wn >> 1) * (2 * C1);
#pragma unroll
        for (int mt = 0; mt < 9; mt++) {
            float pd0 = 0.f, ps0 = 0.f, pd8 = 0.f, ps8 = 0.f;
#pragma unroll
            for (int nt = 0; nt < 4; nt++) {
                int col = wn * 32 + nt * 8 + (lane & 3) * 2;
                int cidx = col & 63;
                float ad0 = __ldg(att + cidx),      ad1 = __ldg(att + cidx + 1);
                float as0 = __ldg(att + 64 + cidx), as1 = __ldg(att + 64 + cidx + 1);
                pd0 += acc[mt][nt][0] * ad0 + acc[mt][nt][1] * ad1;
                ps0 += acc[mt][nt][0] * as0 + acc[mt][nt][1] * as1;
                pd8 += acc[mt][nt][2] * ad0 + acc[mt][nt][3] * ad1;
                ps8 += acc[mt][nt][2] * as0 + acc[mt][nt][3] * as1;
            }
#pragma unroll
            for (int o = 1; o <= 2; o <<= 1) {
                pd0 += __shfl_xor_sync(0xffffffffu, pd0, o);
                ps0 += __shfl_xor_sync(0xffffffffu, ps0, o);
                pd8 += __shfl_xor_sync(0xffffffffu, pd8, o);
                ps8 += __shfl_xor_sync(0xffffffffu, ps8, o);
            }
            if ((lane & 3) == 0) {
                int rl = mt * 16 + (lane >> 2);
                sbufD[wn * MT + rl] = pd0;  sbufS[wn * MT + rl] = ps0;
                sbufD[wn * MT + rl + 8] = pd8;  sbufS[wn * MT + rl + 8] = ps8;
            }
        }
        __syncthreads();

        float mxd = -1e30f, mxs = -1e30f;
        for (int t = tid; t < MT * 4; t += 256) {
            int r = t >> 2, h = t & 3;
            int row = bm + r;
            if (row >= M) continue;
            float dsum = sbufD[(2 * h) * MT + r] + sbufD[(2 * h + 1) * MT + r];
            float ssum = sbufS[(2 * h) * MT + r] + sbufS[(2 * h + 1) * MT + r];
            sdo[row * 4 + h] = dsum;
            sso[row * 4 + h] = ssum;
            mxd = fmaxf(mxd, dsum);
            mxs = fmaxf(mxs, ssum);
        }
#pragma unroll
        for (int o = 16; o; o >>= 1) {
            mxd = fmaxf(mxd, __shfl_xor_sync(0xffffffffu, mxd, o));
            mxs = fmaxf(mxs, __shfl_xor_sync(0xffffffffu, mxs, o));
        }
        if (lane == 0) { atomicMaxF(&smax[0], mxd); atomicMaxF(&smax[1], mxs); }
    }
}

// ---------------- gemm23 (bf16-staged, fp16 C, mu/lv scores) ---------------------
#define PSA_H 0
#define PSA_L 18432
#define PSB_H 36864
#define PSB_L 69632
#define PBUF  102400

__global__ void __launch_bounds__(256)
gemm_mma2(const __nv_bfloat16* __restrict__ Ahi, const __nv_bfloat16* __restrict__ Alo,
          const __nv_bfloat16* __restrict__ Bhi, const __nv_bfloat16* __restrict__ Blo,
          __half* __restrict__ C, int M, int K,
          const float* __restrict__ attP, const float* __restrict__ attQ,
          float* __restrict__ sdo, float* __restrict__ sso,
          float* __restrict__ smax) {
    extern __shared__ char smem[];
    const uint32_t sb = (uint32_t)__cvta_generic_to_shared(smem);
    const int tid = threadIdx.x, wn = tid >> 5, lane = tid & 31;
    const int bm = blockIdx.y * MT;
    const int N = 256;

    float acc[9][4][4];
#pragma unroll
    for (int i = 0; i < 9; i++)
#pragma unroll
        for (int j = 0; j < 4; j++)
#pragma unroll
            for (int q = 0; q < 4; q++) acc[i][j][q] = 0.f;

    const int a_lrow = lane & 15;
    const int a_lbyte = ((lane >> 4) & 1) * 16;
    const int b_lrow = lane & 7;
    const int b_lbyte = ((lane >> 3) & 1) * 16;
    const int nchunks = K >> 6;

    auto stage = [&](int c, int buf) {
        const int k0 = c << 6;
        const uint32_t bufo = sb + buf * PBUF;
        for (int u = tid; u < MT * 8; u += 256) {
            int row = u >> 3, ch = u & 7;
            uint32_t soff = SWZ((uint32_t)(row * 128 + ch * 16));
            int arow = bm + row; if (arow >= M) arow = M - 1;
            size_t aidx = (size_t)arow * K + k0 + ch * 8;
            cp16(bufo + PSA_H + soff, Ahi + aidx);
            cp16(bufo + PSA_L + soff, Alo + aidx);
        }
        for (int u = tid; u < 256 * 8; u += 256) {
            int row = u >> 3, ch = u & 7;
            uint32_t soff = SWZ((uint32_t)(row * 128 + ch * 16));
            size_t bidx = (size_t)row * K + k0 + ch * 8;
            cp16(bufo + PSB_H + soff, Bhi + bidx);
            cp16(bufo + PSB_L + soff, Blo + bidx);
        }
        cp_commit();
    };

    stage(0, 0);
    for (int c = 0; c < nchunks; c++) {
        if (c + 1 < nchunks) { stage(c + 1, (c + 1) & 1); cp_wait<1>(); }
        else                 { cp_wait<0>(); }
        __syncthreads();
        const uint32_t bufo = sb + (c & 1) * PBUF;
#pragma unroll
        for (int ks = 0; ks < 4; ks++) {
            const int kb = ks * 32;
            uint32_t bh[4][2], bl[4][2];
#pragma unroll
            for (int nt = 0; nt < 4; nt++) {
                int row = wn * 32 + nt * 8 + b_lrow;
                uint32_t off = SWZ((uint32_t)(row * 128 + kb + b_lbyte));
                ldsm_x2(bh[nt][0], bh[nt][1], bufo + PSB_H + off);
                ldsm_x2(bl[nt][0], bl[nt][1], bufo + PSB_L + off);
            }
#pragma unroll
            for (int mt = 0; mt < 9; mt++) {
                uint32_t ah[4], al[4];
                int row = mt * 16 + a_lrow;
                uint32_t off = SWZ((uint32_t)(row * 128 + kb + a_lbyte));
                ldsm_x4(ah[0], ah[1], ah[2], ah[3], bufo + PSA_H + off);
                ldsm_x4(al[0], al[1], al[2], al[3], bufo + PSA_L + off);
#pragma unroll
                for (int nt = 0; nt < 4; nt++) {
                    mma16816(acc[mt][nt], ah, bh[nt]);
                    mma16816(acc[mt][nt], ah, bl[nt]);
                    mma16816(acc[mt][nt], al, bh[nt]);
                }
            }
        }
        __syncthreads();
    }

#pragma unroll
    for (int mt = 0; mt < 9; mt++) {
        int r0 = bm + mt * 16 + (lane >> 2);
#pragma unroll
        for (int nt = 0; nt < 4; nt++) {
            int col = wn * 32 + nt * 8 + (lane & 3) * 2;
            if (r0 < M)
                *(__half2*)(C + (size_t)r0 * N + col) =
                    __floats2half2_rn(acc[mt][nt][0], acc[mt][nt][1]);
            if (r0 + 8 < M)
                *(__half2*)(C + (size_t)(r0 + 8) * N + col) =
                    __floats2half2_rn(acc[mt][nt][2], acc[mt][nt][3]);
        }
    }

    {
        float* sbufD = (float*)smem;
        float* sbufS = sbufD + 8 * MT;
        const float* att = (wn >> 2) ? attQ : attP;
#pragma unroll
        for (int mt = 0; mt < 9; mt++) {
            float pd0 = 0.f, ps0 = 0.f, pd8 = 0.f, ps8 = 0.f;
#pragma unroll
            for (int nt = 0; nt < 4; nt++) {
                int col = wn * 32 + nt * 8 + (lane & 3) * 2;
                int cidx = col & 127;
                float ad0 = __ldg(att + cidx),        ad1 = __ldg(att + cidx + 1);
                float as0 = __ldg(att + 128 + cidx),  as1 = __ldg(att + 128 + cidx + 1);
                pd0 += acc[mt][nt][0] * ad0 + acc[mt][nt][1] * ad1;
                ps0 += acc[mt][nt][0] * as0 + acc[mt][nt][1] * as1;
                pd8 += acc[mt][nt][2] * ad0 + acc[mt][nt][3] * ad1;
                ps8 += acc[mt][nt][2] * as0 + acc[mt][nt][3] * as1;
            }
#pragma unroll
            for (int o = 1; o <= 2; o <<= 1) {
                pd0 += __shfl_xor_sync(0xffffffffu, pd0, o);
                ps0 += __shfl_xor_sync(0xffffffffu, ps0, o);
                pd8 += __shfl_xor_sync(0xffffffffu, pd8, o);
                ps8 += __shfl_xor_sync(0xffffffffu, ps8, o);
            }
            if ((lane & 3) == 0) {
                int rl = mt * 16 + (lane >> 2);
                sbufD[wn * MT + rl] = pd0;  sbufS[wn * MT + rl] = ps0;
                sbufD[wn * MT + rl + 8] = pd8;  sbufS[wn * MT + rl + 8] = ps8;
            }
        }
        __syncthreads();

        float mxd = -1e30f, mxs = -1e30f;
        int mysel = tid & 1;
        for (int t = tid; t < MT * 2; t += 256) {
            int r = t >> 1, sel = t & 1;
            int row = bm + r;
            if (row >= M) continue;
            float dsum = 0.f, ssum = 0.f;
#pragma unroll
            for (int w = 0; w < 4; w++) {
                dsum += sbufD[(sel * 4 + w) * MT + r];
                ssum += sbufS[(sel * 4 + w) * MT + r];
            }
            sdo[row * 2 + sel] = dsum;
            sso[row * 2 + sel] = ssum;
            mxd = fmaxf(mxd, dsum);
            mxs = fmaxf(mxs, ssum);
        }
#pragma unroll
        for (int o = 2; o <= 16; o <<= 1) {
            mxd = fmaxf(mxd, __shfl_xor_sync(0xffffffffu, mxd, o));
            mxs = fmaxf(mxs, __shfl_xor_sync(0xffffffffu, mxs, o));
        }
        if (lane < 2) {
            atomicMaxF(&smax[2 + 2 * mysel], mxd);
            atomicMaxF(&smax[3 + 2 * mysel], mxs);
        }
    }
}

// ---------------- layer-1 per-node aggregation (fp16 gathers) -------------------
// One warp per node; lane covers 8 contiguous cols (head = lane>>3).
__global__ void agg1(const int* __restrict__ rowstart, const int2* __restrict__ epack,
                     const float* __restrict__ sd, const float* __restrict__ ss,
                     const float* __restrict__ smax, const __half* __restrict__ xp,
                     const float* __restrict__ bias,
                     uint4* __restrict__ hhi, uint4* __restrict__ hlo) {
    int d = (blockIdx.x * blockDim.x + threadIdx.x) >> 5;
    int lane = threadIdx.x & 31;
    if (d >= NN) return;
    const float M = leaky(__ldg(&smax[0]) + __ldg(&smax[1]));
    const int head = lane >> 3;
    float4 sdv = *(const float4*)(sd + d * 4);
    const float sdh = head == 0 ? sdv.x : head == 1 ? sdv.y : head == 2 ? sdv.z : sdv.w;

    float acc[8];
#pragma unroll
    for (int j = 0; j < 8; j++) acc[j] = 0.f;
    float den = 0.f;

    const int beg = rowstart[d], end = rowstart[d + 1];
    int i = beg;
    for (; i + 1 < end; i += 2) {
        int2 pa = epack[i], pb = epack[i + 1];
        float wa = __int_as_float(pa.y), wb = __int_as_float(pb.y);
        float4 ssa4 = *(const float4*)(ss + pa.x * 4);
        float4 ssb4 = *(const float4*)(ss + pb.x * 4);
        uint4 ha = *(const uint4*)(xp + (size_t)pa.x * HID + lane * 8);
        uint4 hb = *(const uint4*)(xp + (size_t)pb.x * HID + lane * 8);

        float ssa = head == 0 ? ssa4.x : head == 1 ? ssa4.y : head == 2 ? ssa4.z : ssa4.w;
        float exa = expf(leaky(sdh + ssa) - M);
        den += exa;
        float ca = exa * wa;
        float2 f;
        f = __half22float2(*(__half2*)&ha.x); acc[0] = fmaf(ca, f.x, acc[0]); acc[1] = fmaf(ca, f.y, acc[1]);
        f = __half22float2(*(__half2*)&ha.y); acc[2] = fmaf(ca, f.x, acc[2]); acc[3] = fmaf(ca, f.y, acc[3]);
        f = __half22float2(*(__half2*)&ha.z); acc[4] = fmaf(ca, f.x, acc[4]); acc[5] = fmaf(ca, f.y, acc[5]);
        f = __half22float2(*(__half2*)&ha.w); acc[6] = fmaf(ca, f.x, acc[6]); acc[7] = fmaf(ca, f.y, acc[7]);

        float ssb = head == 0 ? ssb4.x : head == 1 ? ssb4.y : head == 2 ? ssb4.z : ssb4.w;
        float exb = expf(leaky(sdh + ssb) - M);
        den += exb;
        float cb = exb * wb;
        f = __half22float2(*(__half2*)&hb.x); acc[0] = fmaf(cb, f.x, acc[0]); acc[1] = fmaf(cb, f.y, acc[1]);
        f = __half22float2(*(__half2*)&hb.y); acc[2] = fmaf(cb, f.x, acc[2]); acc[3] = fmaf(cb, f.y, acc[3]);
        f = __half22float2(*(__half2*)&hb.z); acc[4] = fmaf(cb, f.x, acc[4]); acc[5] = fmaf(cb, f.y, acc[5]);
        f = __half22float2(*(__half2*)&hb.w); acc[6] = fmaf(cb, f.x, acc[6]); acc[7] = fmaf(cb, f.y, acc[7]);
    }
    if (i < end) {
        int2 p = epack[i];
        float w = __int_as_float(p.y);
        float4 ssv4 = *(const float4*)(ss + p.x * 4);
        uint4 h = *(const uint4*)(xp + (size_t)p.x * HID + lane * 8);
        float ssh = head == 0 ? ssv4.x : head == 1 ? ssv4.y : head == 2 ? ssv4.z : ssv4.w;
        float ex = expf(leaky(sdh + ssh) - M);
        den += ex;
        float cc = ex * w;
        float2 f;
        f = __half22float2(*(__half2*)&h.x); acc[0] = fmaf(cc, f.x, acc[0]); acc[1] = fmaf(cc, f.y, acc[1]);
        f = __half22float2(*(__half2*)&h.y); acc[2] = fmaf(cc, f.x, acc[2]); acc[3] = fmaf(cc, f.y, acc[3]);
        f = __half22float2(*(__half2*)&h.z); acc[4] = fmaf(cc, f.x, acc[4]); acc[5] = fmaf(cc, f.y, acc[5]);
        f = __half22float2(*(__half2*)&h.w); acc[6] = fmaf(cc, f.x, acc[6]); acc[7] = fmaf(cc, f.y, acc[7]);
    }

    const float r = 1.f / (den + EPS_F);
    const float4 b0 = *(const float4*)(bias + lane * 8);
    const float4 b1v = *(const float4*)(bias + lane * 8 + 4);
    float o[8];
    float v;
    v = acc[0] * r + b0.x;  o[0] = v > 0.f ? v : expm1f(v);
    v = acc[1] * r + b0.y;  o[1] = v > 0.f ? v : expm1f(v);
    v = acc[2] * r + b0.z;  o[2] = v > 0.f ? v : expm1f(v);
    v = acc[3] * r + b0.w;  o[3] = v > 0.f ? v : expm1f(v);
    v = acc[4] * r + b1v.x; o[4] = v > 0.f ? v : expm1f(v);
    v = acc[5] * r + b1v.y; o[5] = v > 0.f ? v : expm1f(v);
    v = acc[6] * r + b1v.z; o[6] = v > 0.f ? v : expm1f(v);
    v = acc[7] * r + b1v.w; o[7] = v > 0.f ? v : expm1f(v);

    uint4 hv, lv;
    split2(o[0], o[1], hv.x, lv.x);
    split2(o[2], o[3], hv.y, lv.y);
    split2(o[4], o[5], hv.z, lv.z);
    split2(o[6], o[7], hv.w, lv.w);
    hhi[(size_t)d * 32 + lane] = hv;
    hlo[(size_t)d * 32 + lane] = lv;
}

// ---------------- mu/lv per-node aggregation (fp16 gathers) ---------------------
__global__ void agg23(const int* __restrict__ rowstart, const int2* __restrict__ epack,
                      const float* __restrict__ sd23, const float* __restrict__ ss23,
                      const float* __restrict__ smax, const __half* __restrict__ hp,
                      const float* __restrict__ bmu, const float* __restrict__ blv,
                      float* __restrict__ omu, float* __restrict__ olv) {
    int d = (blockIdx.x * blockDim.x + threadIdx.x) >> 5;
    int lane = threadIdx.x & 31;
    if (d >= NN) return;
    const int sel = lane >> 4;   // 0: mu (cols 0-127), 1: lv (cols 128-255)
    const float Msel = sel ? leaky(__ldg(&smax[4]) + __ldg(&smax[5]))
                           : leaky(__ldg(&smax[2]) + __ldg(&smax[3]));
    float2 sdv = ((const float2*)sd23)[d];
    const float sdh = sel ? sdv.y : sdv.x;

    float acc[8];
#pragma unroll
    for (int j = 0; j < 8; j++) acc[j] = 0.f;
    float den = 0.f;

    const int beg = rowstart[d], end = rowstart[d + 1];
    int i = beg;
    for (; i + 1 < end; i += 2) {
        int2 pa = epack[i], pb = epack[i + 1];
        float wa = __int_as_float(pa.y), wb = __int_as_float(pb.y);
        float2 ssa2 = ((const float2*)ss23)[pa.x];
        float2 ssb2 = ((const float2*)ss23)[pb.x];
        uint4 ha = *(const uint4*)(hp + (size_t)pa.x * 256 + lane * 8);
        uint4 hb = *(const uint4*)(hp + (size_t)pb.x * 256 + lane * 8);

        float exa = expf(leaky(sdh + (sel ? ssa2.y : ssa2.x)) - Msel);
        den += exa;
        float ca = exa * wa;
        float2 f;
        f = __half22float2(*(__half2*)&ha.x); acc[0] = fmaf(ca, f.x, acc[0]); acc[1] = fmaf(ca, f.y, acc[1]);
        f = __half22float2(*(__half2*)&ha.y); acc[2] = fmaf(ca, f.x, acc[2]); acc[3] = fmaf(ca, f.y, acc[3]);
        f = __half22float2(*(__half2*)&ha.z); acc[4] = fmaf(ca, f.x, acc[4]); acc[5] = fmaf(ca, f.y, acc[5]);
        f = __half22float2(*(__half2*)&ha.w); acc[6] = fmaf(ca, f.x, acc[6]); acc[7] = fmaf(ca, f.y, acc[7]);

        float exb = expf(leaky(sdh + (sel ? ssb2.y : ssb2.x)) - Msel);
        den += exb;
        float cb = exb * wb;
        f = __half22float2(*(__half2*)&hb.x); acc[0] = fmaf(cb, f.x, acc[0]); acc[1] = fmaf(cb, f.y, acc[1]);
        f = __half22float2(*(__half2*)&hb.y); acc[2] = fmaf(cb, f.x, acc[2]); acc[3] = fmaf(cb, f.y, acc[3]);
        f = __half22float2(*(__half2*)&hb.z); acc[4] = fmaf(cb, f.x, acc[4]); acc[5] = fmaf(cb, f.y, acc[5]);
        f = __half22float2(*(__half2*)&hb.w); acc[6] = fmaf(cb, f.x, acc[6]); acc[7] = fmaf(cb, f.y, acc[7]);
    }
    if (i < end) {
        int2 p = epack[i];
        float w = __int_as_float(p.y);
        float2 ssv2 = ((const float2*)ss23)[p.x];
        uint4 h = *(const uint4*)(hp + (size_t)p.x * 256 + lane * 8);
        float ex = expf(leaky(sdh + (sel ? ssv2.y : ssv2.x)) - Msel);
        den += ex;
        float cc = ex * w;
        float2 f;
        f = __half22float2(*(__half2*)&h.x); acc[0] = fmaf(cc, f.x, acc[0]); acc[1] = fmaf(cc, f.y, acc[1]);
        f = __half22float2(*(__half2*)&h.y); acc[2] = fmaf(cc, f.x, acc[2]); acc[3] = fmaf(cc, f.y, acc[3]);
        f = __half22float2(*(__half2*)&h.z); acc[4] = fmaf(cc, f.x, acc[4]); acc[5] = fmaf(cc, f.y, acc[5]);
        f = __half22float2(*(__half2*)&h.w); acc[6] = fmaf(cc, f.x, acc[6]); acc[7] = fmaf(cc, f.y, acc[7]);
    }

    const float r = 1.f / (den + EPS_F);
    const int cc = (lane & 15) * 8;
    const float* bias = sel ? blv : bmu;
    float* outp = sel ? olv : omu;
    const float4 b0 = *(const float4*)(bias + cc);
    const float4 b1v = *(const float4*)(bias + cc + 4);
    float4 o0 = make_float4(acc[0] * r + b0.x, acc[1] * r + b0.y,
                            acc[2] * r + b0.z, acc[3] * r + b0.w);
    float4 o1 = make_float4(acc[4] * r + b1v.x, acc[5] * r + b1v.y,
                            acc[6] * r + b1v.z, acc[7] * r + b1v.w);
    *(float4*)(outp + (size_t)d * LAT + cc) = o0;
    *(float4*)(outp + (size_t)d * LAT + cc + 4) = o1;
}

// ---------------- launch --------------------------------------------------------
static inline int cdiv(int a, int b) { return (a + b - 1) / b; }

struct PersistCtx {
    cudaStream_t s1;
    cudaEvent_t evRoot, evPrep, evSort;
    PersistCtx() {
        cudaStreamCreateWithFlags(&s1, cudaStreamNonBlocking);
        cudaEventCreateWithFlags(&evRoot, cudaEventDisableTiming);
        cudaEventCreateWithFlags(&evPrep, cudaEventDisableTiming);
        cudaEventCreateWithFlags(&evSort, cudaEventDisableTiming);
    }
};

extern "C" void kernel_launch(void* const* d_in, const int* in_sizes, int n_in,
                              void* d_out, int out_size) {
    static PersistCtx ctx;

    const float* x     = (const float*)d_in[0];
    const int*   ei    = (const int*)  d_in[1];
    const float* ew    = (const float*)d_in[2];
    const float* W1    = (const float*)d_in[3];
    const float* att1  = (const float*)d_in[4];
    const float* b1    = (const float*)d_in[5];
    const float* Wmu   = (const float*)d_in[6];
    const float* attmu = (const float*)d_in[7];
    const float* bmu   = (const float*)d_in[8];
    const float* Wlv   = (const float*)d_in[9];
    const float* attlv = (const float*)d_in[10];
    const float* blv   = (const float*)d_in[11];

    const int* src = ei;
    const int* dst = ei + NE;
    float* out_mu = (float*)d_out;
    float* out_lv = out_mu + (size_t)NN * LAT;

    __half *xph, *hp23h;
    float *sd1, *ss1, *sd23, *ss23, *smax;
    __nv_bfloat16 *hhi, *hlo, *bt1h, *bt1l, *bt23h, *bt23l;
    int *rowstart, *cursor;
    int2 *epack;
    cudaGetSymbolAddress((void**)&xph,   g_xph);
    cudaGetSymbolAddress((void**)&hp23h, g_hp23h);
    cudaGetSymbolAddress((void**)&hhi,   g_hhi);
    cudaGetSymbolAddress((void**)&hlo,   g_hlo);
    cudaGetSymbolAddress((void**)&bt1h,  g_bt1h);
    cudaGetSymbolAddress((void**)&bt1l,  g_bt1l);
    cudaGetSymbolAddress((void**)&bt23h, g_bt23h);
    cudaGetSymbolAddress((void**)&bt23l, g_bt23l);
    cudaGetSymbolAddress((void**)&sd1,   g_sd1);
    cudaGetSymbolAddress((void**)&ss1,   g_ss1);
    cudaGetSymbolAddress((void**)&sd23,  g_sd23);
    cudaGetSymbolAddress((void**)&ss23,  g_ss23);
    cudaGetSymbolAddress((void**)&smax,  g_smax);
    cudaGetSymbolAddress((void**)&rowstart, g_rowstart);
    cudaGetSymbolAddress((void**)&cursor,   g_cursor);
    cudaGetSymbolAddress((void**)&epack,    g_epack);

    cudaFuncSetAttribute(gemm_conv, cudaFuncAttributeMaxDynamicSharedMemorySize, CF_TOTAL);
    cudaFuncSetAttribute(gemm_mma2, cudaFuncAttributeMaxDynamicSharedMemorySize, 2 * PBUF);

    const int TB = 256;
    const int MGRID = cdiv(NN, MT);
    cudaStream_t s1 = ctx.s1;

    cudaEventRecord(ctx.evRoot, 0);
    cudaStreamWaitEvent(s1, ctx.evRoot, 0);

    // ----- s1: weight prep (+cursor zero), then edge sort chain -----
    prepW<<<cdiv(HID * FIN, TB), TB, 0, s1>>>(W1, bt1h, bt1l, Wmu, Wlv, bt23h, bt23l,
                                              smax, cursor);
    cudaEventRecord(ctx.evPrep, s1);
    hist_kernel<<<cdiv(NE, TB), TB, 0, s1>>>(dst, cursor);
    scan_kernel<<<1, 1024, 0, s1>>>(cursor, rowstart, cursor);
    fillsort_kernel<<<cdiv(NE, TB), TB, 0, s1>>>(src, dst, ew, cursor, epack);
    cudaEventRecord(ctx.evSort, s1);

    // ----- s0 (legacy): main chain -----
    cudaStreamWaitEvent(0, ctx.evPrep, 0);
    gemm_conv<<<dim3(1, MGRID), 256, CF_TOTAL>>>(
        x, bt1h, bt1l, xph, NN, FIN, att1, sd1, ss1, smax);
    cudaStreamWaitEvent(0, ctx.evSort, 0);
    agg1<<<cdiv(NN * 32, TB), TB>>>(rowstart, epack, sd1, ss1, smax, xph, b1,
                                    (uint4*)hhi, (uint4*)hlo);
    gemm_mma2<<<dim3(1, MGRID), 256, 2 * PBUF>>>(
        hhi, hlo, bt23h, bt23l, hp23h, NN, HID, attmu, attlv, sd23, ss23, smax);
    agg23<<<cdiv(NN * 32, TB), TB>>>(rowstart, epack, sd23, ss23, smax,
                                     hp23h, bmu, blv, out_mu, out_lv);
}